// round 11
// baseline (speedup 1.0000x reference)
#include <cuda_runtime.h>
#include <cuda_bf16.h>
#include <cstdint>

// ---------------- problem constants ----------------
#define NB    128
#define CIN   1024
#define HH    14
#define WW    14
#define OO    196
#define CF    128
#define TH    128
#define QD    258
#define CED   130
#define PD    388
#define HP    256
#define GT    256
#define FP    256
#define ASZ   32

// ---------------- scratch ----------------
__device__ __align__(16) __nv_bfloat16 g_imh[NB * 256 * CIN];
__device__ __align__(16) __nv_bfloat16 g_iml[NB * 256 * CIN];
__device__ __align__(16) uint8_t g_wbh[144 * 16384];
__device__ __align__(16) uint8_t g_wbl[144 * 16384];
__device__ __align__(16) float g_xt[NB * OO * CF];
__device__ __align__(16) __nv_bfloat16 g_xth[NB * OO * CF];
__device__ __align__(16) __nv_bfloat16 g_xtl[NB * OO * CF];
__device__ __align__(16) uint8_t g_hpBh[4 * 16384],  g_hpBl[4 * 16384];
__device__ __align__(16) uint8_t g_gt0Bh[4 * 16384], g_gt0Bl[4 * 16384];
__device__ __align__(16) uint8_t g_gt1Bh[8 * 16384], g_gt1Bl[8 * 16384];
__device__ float g_pero_hp[OO * 256], g_pern_hp[NB * 256];
__device__ float g_pero_gt[OO * 256], g_pern_gt[NB * 256];
__device__ float g_att[NB * OO];
__device__ float g_sel[NB * CED];
__device__ float g_rel[NB * GT];

__device__ __forceinline__ float xcoord(int o) { return -1.0f + 2.0f * (float)(o / WW) / 13.0f; }
__device__ __forceinline__ float ycoord(int o) { return -1.0f + 2.0f * (float)(o % WW) / 13.0f; }

// ---------------- helpers ----------------
#define SWZ(x) ((x) ^ (((x) >> 3) & 0x70))

__device__ __forceinline__ uint32_t smem_u32(const void* p) {
    uint32_t a;
    asm("{ .reg .u64 t; cvta.to.shared.u64 t, %1; cvt.u32.u64 %0, t; }" : "=r"(a) : "l"(p));
    return a;
}
__device__ __forceinline__ void ldsm_x4(uint32_t* r, uint32_t addr) {
    asm volatile("ldmatrix.sync.aligned.m8n8.x4.shared.b16 {%0,%1,%2,%3}, [%4];"
                 : "=r"(r[0]), "=r"(r[1]), "=r"(r[2]), "=r"(r[3]) : "r"(addr));
}
__device__ __forceinline__ void mma16816(float* c, const uint32_t* a, uint32_t b0, uint32_t b1) {
    asm volatile("mma.sync.aligned.m16n8k16.row.col.f32.bf16.bf16.f32 "
                 "{%0,%1,%2,%3}, {%4,%5,%6,%7}, {%8,%9}, {%0,%1,%2,%3};"
                 : "+f"(c[0]), "+f"(c[1]), "+f"(c[2]), "+f"(c[3])
                 : "r"(a[0]), "r"(a[1]), "r"(a[2]), "r"(a[3]), "r"(b0), "r"(b1));
}
__device__ __forceinline__ void cp16(uint32_t dst, const void* src) {
    asm volatile("cp.async.cg.shared.global [%0], [%1], 16;" :: "r"(dst), "l"(src));
}
__device__ __forceinline__ void cp_commit() { asm volatile("cp.async.commit_group;" ::: "memory"); }
__device__ __forceinline__ void bf16split(float v, __nv_bfloat16& h, __nv_bfloat16& l) {
    h = __float2bfloat16(v);
    l = __float2bfloat16(v - __bfloat162float(h));
}

// ---------------- mega prep kernel ----------------
#define PREP_BLOCKS 27460

__device__ __forceinline__ void mlppack_one(const float* __restrict__ src,
                                            uint8_t* __restrict__ dstH,
                                            uint8_t* __restrict__ dstL, int idx) {
    int k6    = idx & 63;
    int ch    = (idx >> 6) & 127;
    int chblk = (idx >> 13) & 1;
    int kblk  = idx >> 14;
    float v = src[(kblk * 64 + k6) * 256 + chblk * 128 + ch];
    __nv_bfloat16 hi, lo; bf16split(v, hi, lo);
    int off = (kblk * 2 + chblk) * 16384 + SWZ(ch * 128 + k6 * 2);
    *(__nv_bfloat16*)(dstH + off) = hi;
    *(__nv_bfloat16*)(dstL + off) = lo;
}

__global__ void __launch_bounds__(256) k_prep_all(
    const float* __restrict__ image, const float* __restrict__ conv_w,
    const float* __restrict__ code,
    const float* __restrict__ hp_w0, const float* __restrict__ hp_b0,
    const float* __restrict__ gt_w0, const float* __restrict__ gt_b0,
    const float* __restrict__ gt_w1)
{
    int b = blockIdx.x, tid = threadIdx.x;

    if (b < 4608) {                       // conv weight pack
        int idx = b * 256 + tid;
        int j    = idx & 63;
        int ch   = (idx >> 6) & 127;
        int cb   = (idx >> 13) & 15;
        int kykx = idx >> 17;
        int cin  = cb * 64 + j;
        float v = conv_w[ch * (CIN * 9) + cin * 9 + kykx];
        __nv_bfloat16 hi, lo; bf16split(v, hi, lo);
        int dst = (kykx * 16 + cb) * 16384 + SWZ(ch * 128 + j * 2);
        *(__nv_bfloat16*)(g_wbh + dst) = hi;
        *(__nv_bfloat16*)(g_wbl + dst) = lo;
    } else if (b < 4736) {
        mlppack_one(hp_w0, g_hpBh, g_hpBl, (b - 4608) * 256 + tid);
    } else if (b < 4864) {
        mlppack_one(gt_w0, g_gt0Bh, g_gt0Bl, (b - 4736) * 256 + tid);
    } else if (b < 5120) {
        mlppack_one(gt_w1, g_gt1Bh, g_gt1Bl, (b - 4864) * 256 + tid);
    } else if (b < 12800) {               // halo border zero
        int e = (b - 5120) * 256 + tid;
        int arr = e >= 983040;
        int j = e - arr * 983040;
        int n  = j / (60 * 128);
        int r  = j - n * (60 * 128);
        int bp = r >> 7, u = r & 127;
        int hp;
        if (bp < 16)      hp = bp;
        else if (bp < 32) hp = 240 + (bp - 16);
        else { int i = bp - 32; int hr = 1 + (i >> 1); int hc = (i & 1) ? 15 : 0; hp = hr * 16 + hc; }
        uint4 z = {0, 0, 0, 0};
        size_t o4 = (size_t)(n * 256 + hp) * 128 + u;
        if (arr) ((uint4*)g_iml)[o4] = z; else ((uint4*)g_imh)[o4] = z;
    } else if (b < 27136) {               // image transpose + split
        int bb = b - 12800;
        int pb = bb % 7, cbk = (bb / 7) % 16, n = bb / 112;
        __shared__ float t[64][33];
        int pos0 = pb * 32;
        for (int e = tid; e < 64 * 32; e += 256) {
            int ci = e >> 5, p = e & 31;
            int pos = pos0 + p;
            float v = 0.0f;
            if (pos < OO) v = image[((size_t)n * CIN + cbk * 64 + ci) * OO + pos];
            t[ci][p] = v;
        }
        __syncthreads();
        for (int e = tid; e < 64 * 32; e += 256) {
            int p = e >> 6, ci = e & 63;
            int pos = pos0 + p;
            if (pos < OO) {
                int row = pos / 14, col = pos - row * 14;
                int hp  = (row + 1) * 16 + (col + 1);
                size_t off = ((size_t)n * 256 + hp) * 1024 + cbk * 64 + ci;
                __nv_bfloat16 hi, lo; bf16split(t[ci][p], hi, lo);
                g_imh[off] = hi;
                g_iml[off] = lo;
            }
        }
    } else if (b < 27332) {               // per-o tables
        int o = b - 27136, ch = tid;
        float xc = xcoord(o), yc = ycoord(o);
        g_pero_hp[o * 256 + ch] = xc * hp_w0[128 * 256 + ch] + yc * hp_w0[129 * 256 + ch];
        g_pero_gt[o * 256 + ch] = xc * gt_w0[128 * 256 + ch] + yc * gt_w0[129 * 256 + ch];
    } else {                              // per-n tables + zero rel
        int n = b - 27332, ch = tid;
        float sh = hp_b0[ch], sg = gt_b0[ch];
#pragma unroll 4
        for (int d = 0; d < 128; d++) {
            float c = code[n * 128 + d];
            sh = fmaf(c, hp_w0[(130 + d) * 256 + ch], sh);
            sg = fmaf(c, gt_w0[(130 + d) * 256 + ch], sg);
        }
        g_pern_hp[n * 256 + ch] = sh;
        g_pern_gt[n * 256 + ch] = sg;
        g_rel[n * 256 + ch] = 0.0f;
    }
}

// ---------------- conv: 2-way M-split, mma.sync bf16 3-section GEMM ----------------
// 256 CTAs: n = bid>>1, part = bid&1. Part0 units {0..6}, part1 {7..12} (unit = 16 rows).
// 512 thr, 16 warps: wm = wid>>2, wn = wid&3 (SMSP = wn). Units per warp: ubase+wm+4*mf.
__device__ __forceinline__ void prefetch_B3(int g, uint32_t Bb, int tid) {
    int cb = g / 9, kykx = g - cb * 9;
    size_t off = (size_t)(kykx * 16 + cb) * 16384;
    uint32_t dst = Bb + (uint32_t)(g % 3) * 32768;
#pragma unroll
    for (int t = 0; t < 2; t++) {
        int i = tid + t * 512;
        cp16(dst + i * 16,         g_wbh + off + i * 16);
        cp16(dst + 16384 + i * 16, g_wbl + off + i * 16);
    }
}

template<int NMF>
__device__ __forceinline__ void conv_stage(uint32_t haloH, uint32_t haloL, uint32_t Bstage,
                                           int kd, const int* pbA, int chB0, int kHi,
                                           float (*acc)[16]) {
    uint32_t Bh = Bstage, Bl = Bstage + 16384;
#pragma unroll
    for (int ks = 0; ks < 4; ks++) {
        uint32_t bh[2][4], bl[2][4], a[NMF][4];
        uint32_t kof = (uint32_t)(ks * 32 + kHi);
#pragma unroll
        for (int bf = 0; bf < 2; bf++) ldsm_x4(bh[bf], Bh + SWZ((uint32_t)((chB0 + bf * 16) * 128) + kof));
#pragma unroll
        for (int mf = 0; mf < NMF; mf++) ldsm_x4(a[mf], haloH + SWZ((uint32_t)((pbA[mf] + kd) * 128) + kof));
#pragma unroll
        for (int mf = 0; mf < NMF; mf++)
#pragma unroll
            for (int nf = 0; nf < 4; nf++)
                mma16816(&acc[mf][nf * 4], a[mf], bh[nf >> 1][nf & 1], bh[nf >> 1][(nf & 1) + 2]);
#pragma unroll
        for (int bf = 0; bf < 2; bf++) ldsm_x4(bl[bf], Bl + SWZ((uint32_t)((chB0 + bf * 16) * 128) + kof));
#pragma unroll
        for (int mf = 0; mf < NMF; mf++)
#pragma unroll
            for (int nf = 0; nf < 4; nf++)
                mma16816(&acc[mf][nf * 4], a[mf], bl[nf >> 1][nf & 1], bl[nf >> 1][(nf & 1) + 2]);
#pragma unroll
        for (int mf = 0; mf < NMF; mf++) ldsm_x4(a[mf], haloL + SWZ((uint32_t)((pbA[mf] + kd) * 128) + kof));
#pragma unroll
        for (int mf = 0; mf < NMF; mf++)
#pragma unroll
            for (int nf = 0; nf < 4; nf++)
                mma16816(&acc[mf][nf * 4], a[mf], bh[nf >> 1][nf & 1], bh[nf >> 1][(nf & 1) + 2]);
    }
}

__global__ void __launch_bounds__(512) k_conv_mma(const float* __restrict__ conv_b) {
    extern __shared__ char sm_raw[];
    __shared__ float s_bias[128];
    const int tid = threadIdx.x;
    const int n = blockIdx.x >> 1, cpart = blockIdx.x & 1;
    const int wid = tid >> 5, lane = tid & 31;
    const int wm = wid >> 2, wn = wid & 3;
    const int ubase = cpart * 7;
    const int ucnt  = cpart ? 6 : 7;
    const int nmf = (wm + 4 < ucnt) ? 2 : 1;   // wm < ucnt always (ucnt >= 6 > 3)

    uint32_t raw = smem_u32(sm_raw);
    uint32_t base = (raw + 1023u) & ~1023u;
    char* sm = sm_raw + (base - raw);
    const uint32_t haloH = base, haloL = base + 32768, Bb = base + 65536;

    if (tid < 128) s_bias[tid] = conv_b[tid];

    float acc[2][16];
#pragma unroll
    for (int i = 0; i < 2; i++)
#pragma unroll
        for (int j = 0; j < 16; j++) acc[i][j] = 0.0f;

    int pbA[2];
#pragma unroll
    for (int mf = 0; mf < 2; mf++) {
        int u = ubase + wm + 4 * mf;
        if (u > 12) u = 12;
        int o = u * 16 + (lane & 15);
        if (o > 195) o = 195;
        int row = o / 14, col = o - row * 14;
        pbA[mf] = row * 16 + col;
    }
    const int kHi = (lane >> 4) * 16;
    const int chB0 = wn * 32 + (lane & 15);

    prefetch_B3(0, Bb, tid); cp_commit();
    prefetch_B3(1, Bb, tid); cp_commit();

    for (int gs = 0; gs < 144; gs++) {
        int cb = gs / 9, kykx = gs - cb * 9;
        if (kykx == 0) {
            __syncthreads();
#pragma unroll
            for (int t = 0; t < 8; t++) {
                int idx = tid + t * 512;
                int half = idx >> 11;
                int j = idx & 2047;
                int p = j >> 3, u = j & 7;
                const __nv_bfloat16* srcp = (half ? g_iml : g_imh) + ((size_t)n * 256 + p) * 1024 + cb * 64;
                uint4 v = ((const uint4*)srcp)[u];
                *(uint4*)(sm + half * 32768 + SWZ(p * 128 + u * 16)) = v;
            }
        }
        if (gs < 143) asm volatile("cp.async.wait_group 1;" ::: "memory");
        else          asm volatile("cp.async.wait_group 0;" ::: "memory");
        __syncthreads();
        if (gs + 2 < 144) { prefetch_B3(gs + 2, Bb, tid); cp_commit(); }

        int ky = kykx / 3, kx = kykx - ky * 3;
        int kd = ky * 16 + kx;
        uint32_t Bst = Bb + (uint32_t)(gs % 3) * 32768;

        if (nmf == 2) conv_stage<2>(haloH, haloL, Bst, kd, pbA, chB0, kHi, acc);
        else          conv_stage<1>(haloH, haloL, Bst, kd, pbA, chB0, kHi, acc);
    }

    int g = lane >> 2, t2 = (lane & 3) * 2;
    float* dst = g_xt + (size_t)n * OO * CF;
#pragma unroll
    for (int mf = 0; mf < 2; mf++) {
        if (mf < nmf) {
            int u = ubase + wm + 4 * mf;
#pragma unroll
            for (int nf = 0; nf < 4; nf++) {
                int ch = wn * 32 + nf * 8 + t2;
                float b0 = s_bias[ch], b1 = s_bias[ch + 1];
#pragma unroll
                for (int h = 0; h < 2; h++) {
                    int o = u * 16 + g + h * 8;
                    if (o < OO) {
                        float v0 = acc[mf][nf * 4 + h * 2 + 0] + b0;
                        float v1 = acc[mf][nf * 4 + h * 2 + 1] + b1;
                        size_t r = (size_t)n * OO + o;
                        dst[(size_t)o * CF + ch]     = v0;
                        dst[(size_t)o * CF + ch + 1] = v1;
                        __nv_bfloat16 h0, l0, h1, l1;
                        bf16split(v0, h0, l0);
                        bf16split(v1, h1, l1);
                        *(__nv_bfloat162*)(g_xth + r * CF + ch) = __nv_bfloat162{h0, h1};
                        *(__nv_bfloat162*)(g_xtl + r * CF + ch) = __nv_bfloat162{l0, l1};
                    }
                }
            }
        }
    }
}

// ---------------- generic GEMM stage (M=128, 16 warps as 2M x 8N) ----------------
__device__ __forceinline__ void gemm_stage(float (*acc)[16], uint32_t AhT, uint32_t AlT,
                                           uint32_t Bt, bool doLo,
                                           const uint32_t* rbase, uint32_t chbase, uint32_t kHi) {
#pragma unroll
    for (int ks = 0; ks < 4; ks++) {
        uint32_t b[2][4];
        ldsm_x4(b[0], Bt + SWZ(chbase + ks * 32 + kHi));
        ldsm_x4(b[1], Bt + SWZ(chbase + 16 * 128 + ks * 32 + kHi));
#pragma unroll
        for (int mf = 0; mf < 4; mf++) {
            uint32_t a[4];
            ldsm_x4(a, AhT + SWZ(rbase[mf] + ks * 32 + kHi));
#pragma unroll
            for (int nf = 0; nf < 4; nf++)
                mma16816(&acc[mf][nf * 4], a,
                         (nf & 1) ? b[nf >> 1][1] : b[nf >> 1][0],
                         (nf & 1) ? b[nf >> 1][3] : b[nf >> 1][2]);
            if (doLo) {
                uint32_t al[4];
                ldsm_x4(al, AlT + SWZ(rbase[mf] + ks * 32 + kHi));
#pragma unroll
                for (int nf = 0; nf < 4; nf++)
                    mma16816(&acc[mf][nf * 4], al,
                             (nf & 1) ? b[nf >> 1][1] : b[nf >> 1][0],
                             (nf & 1) ? b[nf >> 1][3] : b[nf >> 1][2]);
            }
        }
    }
}

__device__ __forceinline__ void load_A_tile(uint32_t smb, int r0, int tid) {
#pragma unroll
    for (int t = 0; t < 8; t++) {
        int idx = tid + t * 512;
        int half = idx >> 11;
        int j = idx & 2047;
        int row = j >> 4, cc = j & 15;
        int kblk = cc >> 3, u = cc & 7;
        const __nv_bfloat16* src = (half ? g_xtl : g_xth) + (size_t)(r0 + row) * 128 + kblk * 64 + u * 8;
        cp16(smb + half * 32768 + kblk * 16384 + SWZ(row * 128 + u * 16), src);
    }
}

// ---------------- h_psi as GEMM (196 M-tiles) ----------------
__global__ void __launch_bounds__(512) k_hpsi_mma(const float* __restrict__ hp_w1,
                                                  const float* __restrict__ hp_b1) {
    extern __shared__ char sm_raw[];
    __shared__ float s_w1[256];
    __shared__ float attp[8][128];

    const int tid = threadIdx.x;
    const int r0 = blockIdx.x * 128;
    const int wid = tid >> 5, lane = tid & 31;
    const int wm = wid & 1, wn = wid >> 1;

    uint32_t raw = smem_u32(sm_raw);
    uint32_t smb = (raw + 1023u) & ~1023u;
    const uint32_t Bbuf = smb + 65536;

    if (tid < 256) s_w1[tid] = hp_w1[tid];

    uint32_t rbase[4];
#pragma unroll
    for (int mf = 0; mf < 4; mf++) rbase[mf] = (uint32_t)(wm * 64 + mf * 16 + (lane & 15)) * 128;
    const uint32_t kHi = (lane >> 4) * 16;
    const uint32_t chbase = (uint32_t)((wn & 3) * 32 + (lane & 15)) * 128;
    const uint32_t Bwn = (wn >> 2) * 16384;

    float acc[4][16];
#pragma unroll
    for (int i = 0; i < 4; i++)
#pragma unroll
        for (int j = 0; j < 16; j++) acc[i][j] = 0.0f;

    {
        const uint8_t* src = g_hpBh;
#pragma unroll
        for (int t = 0; t < 4; t++) cp16(Bbuf + (tid + t * 512) * 16, src + (tid + t * 512) * 16);
        load_A_tile(smb, r0, tid);
        cp_commit();
    }

    for (int s = 0; s < 4; s++) {
        if (s < 3) {
            int sn = s + 1;
            const uint8_t* src = ((sn & 1) ? g_hpBl : g_hpBh) + (size_t)(sn >> 1) * 32768;
            uint32_t dstb = Bbuf + (sn & 1) * 32768;
#pragma unroll
            for (int t = 0; t < 4; t++) cp16(dstb + (tid + t * 512) * 16, src + (tid + t * 512) * 16);
            cp_commit();
            asm volatile("cp.async.wait_group 1;" ::: "memory");
        } else {
            asm volatile("cp.async.wait_group 0;" ::: "memory");
        }
        __syncthreads();
        int kblk = s >> 1;
        gemm_stage(acc, smb + kblk * 16384, smb + 32768 + kblk * 16384,
                   Bbuf + (s & 1) * 32768 + Bwn, (s & 1) == 0, rbase, chbase, kHi);
        __syncthreads();
    }

    int g = lane >> 2, t2 = (lane & 3) * 2;
    float psum[4][2];
#pragma unroll
    for (int mf = 0; mf < 4; mf++) { psum[mf][0] = 0.0f; psum[mf][1] = 0.0f; }
#pragma unroll
    for (int mf = 0; mf < 4; mf++)
#pragma unroll
        for (int h = 0; h < 2; h++) {
            int row = wm * 64 + mf * 16 + g + h * 8;
            int r = r0 + row;
            int n = r / OO, o = r - n * OO;
#pragma unroll
            for (int nf = 0; nf < 4; nf++)
#pragma unroll
                for (int j = 0; j < 2; j++) {
                    int ch = wn * 32 + nf * 8 + t2 + j;
                    float v = acc[mf][nf * 4 + h * 2 + j] + g_pero_hp[o * 256 + ch] + g_pern_hp[n * 256 + ch];
                    psum[mf][h] += fmaxf(v, 0.0f) * s_w1[ch];
                }
        }
#pragma unroll
    for (int mf = 0; mf < 4; mf++)
#pragma unroll
        for (int h = 0; h < 2; h++) {
            float p = psum[mf][h];
            p += __shfl_xor_sync(0xffffffffu, p, 1);
            p += __shfl_xor_sync(0xffffffffu, p, 2);
            if ((lane & 3) == 0) attp[wn][wm * 64 + mf * 16 + g + h * 8] = p;
        }
    __syncthreads();
    if (tid < 128) {
        float a = hp_b1[0];
#pragma unroll
        for (int w = 0; w < 8; w++) a += attp[w][tid];
        g_att[r0 + tid] = a;
    }
}

// ---------------- fused g_theta (layer1 + layer2 + object-sum) ----------------
__global__ void __launch_bounds__(512) k_gt_mma(const float* __restrict__ gt_b1) {
    extern __shared__ char sm_raw[];
    __shared__ float s_b1[256];
    __shared__ float relp[2][256];

    const int tid = threadIdx.x;
    const int r0 = blockIdx.x * 128;
    const int wid = tid >> 5, lane = tid & 31;
    const int wm = wid & 1, wn = wid >> 1;

    uint32_t raw = smem_u32(sm_raw);
    uint32_t smb = (raw + 1023u) & ~1023u;
    const uint32_t Bbuf = smb + 131072;

    if (tid < 256) s_b1[tid] = gt_b1[tid];
    if (tid < 512) ((float*)relp)[tid] = 0.0f;

    uint32_t rbase[4];
#pragma unroll
    for (int mf = 0; mf < 4; mf++) rbase[mf] = (uint32_t)(wm * 64 + mf * 16 + (lane & 15)) * 128;
    const uint32_t kHi = (lane >> 4) * 16;
    const uint32_t chbase = (uint32_t)((wn & 3) * 32 + (lane & 15)) * 128;
    const uint32_t Bwn = (wn >> 2) * 16384;
    const int g = lane >> 2, t2 = (lane & 3) * 2;

    float acc[4][16];
#pragma unroll
    for (int i = 0; i < 4; i++)
#pragma unroll
        for (int j = 0; j < 16; j++) acc[i][j] = 0.0f;

    {
#pragma unroll
        for (int t = 0; t < 4; t++) cp16(Bbuf + (tid + t * 512) * 16, g_gt0Bh + (tid + t * 512) * 16);
        load_A_tile(smb, r0, tid);
        cp_commit();
    }

    for (int s = 0; s < 12; s++) {
        if (s < 11) {
            int sn = s + 1;
            const uint8_t* basep;
            int kblk;
            if (sn < 4) { basep = (sn & 1) ? g_gt0Bl : g_gt0Bh; kblk = sn >> 1; }
            else        { int t = sn - 4; basep = (t & 1) ? g_gt1Bl : g_gt1Bh; kblk = t >> 1; }
            const uint8_t* src = basep + (size_t)kblk * 32768;
            uint32_t dstb = Bbuf + (sn & 1) * 32768;
#pragma unroll
            for (int t = 0; t < 4; t++) cp16(dstb + (tid + t * 512) * 16, src + (tid + t * 512) * 16);
            cp_commit();
            asm volatile("cp.async.wait_group 1;" ::: "memory");
        } else {
            asm volatile("cp.async.wait_group 0;" ::: "memory");
        }
        __syncthreads();

        if (s < 4) {
            int kblk = s >> 1;
            gemm_stage(acc, smb + kblk * 16384, smb + 32768 + kblk * 16384,
                       Bbuf + (s & 1) * 32768 + Bwn, (s & 1) == 0, rbase, chbase, kHi);
        } else {
            int kt = (s - 4) >> 1;
            gemm_stage(acc, smb + kt * 16384, smb + 65536 + kt * 16384,
                       Bbuf + (s & 1) * 32768 + Bwn, (s & 1) == 0, rbase, chbase, kHi);
        }
        __syncthreads();

        if (s == 3) {
#pragma unroll
            for (int mf = 0; mf < 4; mf++)
#pragma unroll
                for (int h = 0; h < 2; h++) {
                    int row = wm * 64 + mf * 16 + g + h * 8;
                    int r = r0 + row;
                    int n = r / OO, o = r - n * OO;
#pragma unroll
                    for (int nf = 0; nf < 4; nf++) {
                        int ch0 = wn * 32 + nf * 8 + t2;
                        float v0 = acc[mf][nf * 4 + h * 2 + 0] + g_pero_gt[o * 256 + ch0]     + g_pern_gt[n * 256 + ch0];
                        float v1 = acc[mf][nf * 4 + h * 2 + 1] + g_pero_gt[o * 256 + ch0 + 1] + g_pern_gt[n * 256 + ch0 + 1];
                        v0 = fmaxf(v0, 0.0f); v1 = fmaxf(v1, 0.0f);
                        __nv_bfloat16 h0, l0, h1, l1;
                        bf16split(v0, h0, l0);
                        bf16split(v1, h1, l1);
                        uint32_t off = (uint32_t)(ch0 >> 6) * 16384 + SWZ(row * 128 + (ch0 & 63) * 2);
                        *(__nv_bfloat162*)(sm_raw + (smb - raw) + off)         = __nv_bfloat162{h0, h1};
                        *(__nv_bfloat162*)(sm_raw + (smb - raw) + 65536 + off) = __nv_bfloat162{l0, l1};
                    }
                }
#pragma unroll
            for (int i = 0; i < 4; i++)
#pragma unroll
                for (int j = 0; j < 16; j++) acc[i][j] = 0.0f;
            __syncthreads();
        }
    }

    const int n0 = r0 / OO;
    const int n1 = (r0 + 127) / OO;
#pragma unroll
    for (int mf = 0; mf < 4; mf++)
#pragma unroll
        for (int h = 0; h < 2; h++) {
            int row = wm * 64 + mf * 16 + g + h * 8;
            int r = r0 + row;
            int n = r / OO;
            int nn = (n != n0);
#pragma unroll
            for (int nf = 0; nf < 4; nf++)
#pragma unroll
                for (int j = 0; j < 2; j++) {
                    int ch = wn * 32 + nf * 8 + t2 + j;
                    float v = fmaxf(acc[mf][nf * 4 + h * 2 + j] + s_b1[ch], 0.0f);
                    atomicAdd(&relp[nn][ch], v);
                }
        }
    __syncthreads();
    if (tid < 256) {
        atomicAdd(&g_rel[n0 * 256 + tid], relp[0][tid]);
    } else {
        int ch = tid - 256;
        if (n1 != n0) atomicAdd(&g_rel[n1 * 256 + ch], relp[1][ch]);
    }
}

// ---------------- softmax + soft selection + pern_gt finish ----------------
__global__ void __launch_bounds__(256) k_softsel(const float* __restrict__ gt_w0) {
    int n = blockIdx.x;
    int tid = threadIdx.x;
    __shared__ float att_s[OO];
    __shared__ float red_s[8];
    __shared__ float selp[2][128];
    __shared__ float sel_s[CED];

    if (tid < OO) att_s[tid] = g_att[n * OO + tid];
    __syncthreads();

    float v = (tid < OO) ? att_s[tid] : -1e30f;
#pragma unroll
    for (int off = 16; off > 0; off >>= 1) v = fmaxf(v, __shfl_xor_sync(0xffffffffu, v, off));
    if ((tid & 31) == 0) red_s[tid >> 5] = v;
    __syncthreads();
    float m = -1e30f;
#pragma unroll
    for (int i = 0; i < 8; i++) m = fmaxf(m, red_s[i]);
    __syncthreads();

    float e = (tid < OO) ? expf(att_s[tid] - m) : 0.0f;
    float sv = e;
#pragma unroll
    for (int off = 16; off > 0; off >>= 1) sv += __shfl_xor_sync(0xffffffffu, sv, off);
    if ((tid & 31) == 0) red_s[tid >> 5] = sv;
    __syncthreads();
    float tot = 0.0f;
#pragma unroll
    for (int i = 0; i < 8; i++) tot += red_s[i];
    if (tid < OO) att_s[tid] = e / tot;
    __syncthreads();

    // selected: thread owns d; 8 independent accumulators for deep MLP
    {
        const float* xtn = g_xt + (size_t)n * OO * CF;
        int half = tid >> 7, d = tid & 127;
        int o0 = half * 98;
        float a[8];
#pragma unroll
        for (int k = 0; k < 8; k++) a[k] = 0.0f;
#pragma unroll
        for (int i = 0; i < 96; i += 8) {
#pragma unroll
            for (int k = 0; k < 8; k++)
                a[k] = fmaf(att_s[o0 + i + k], xtn[(size_t)(o0 + i + k) * CF + d], a[k]);
        }
        a[0] = fmaf(att_s[o0 + 96], xtn[(size_t)(o0 + 96) * CF + d], a[0]);
        a[1] = fmaf(att_s[o0 + 97], xtn[(size_t)(o0 + 97) * CF + d], a[1]);
        selp[half][d] = ((a[0] + a[1]) + (a[2] + a[3])) + ((a[4] + a[5]) + (a[6] + a[7]));
    }
    __syncthreads();
    if (tid < 128) {
        float s = selp[0][tid] + selp[1][tid];
        g_sel[n * CED + tid] = s;
        sel_s[tid] = s;
    } else if (tid == 128) {
        float a = 0.0f;
        for (int o = 0; o < OO; o++) a = fmaf(att_s[o], xcoord(o), a);
        g_sel[n * CED + 128] = a;
        sel_s[128] = a;
    } else if (tid == 129) {
        float a = 0.0f;
        for (int o = 0; o < OO; o++) a = fmaf(att_s[o], ycoord(o), a);
        g_sel[n * CED + 129] = a;
        sel_s[129] = a;
    }
    __syncthreads();

    // finish pern_gt: add sel . gt_w0[258:388]
    {
        int ch = tid;
        float s = g_pern_gt[n * 256 + ch];
#pragma unroll 2
        for (int d = 0; d < CED; d++)
            s = fmaf(sel_s[d], gt_w0[(QD + d) * 256 + ch], s);
        g_pern_gt[n * 256 + ch] = s;
    }
}

// ---------------- f_phi head ----------------
__global__ void __launch_bounds__(256) k_fphi(const float* __restrict__ fp_w0,
                                              const float* __restrict__ fp_b0,
                                              const float* __restrict__ fp_w1,
                                              const float* __restrict__ fp_b1,
                                              float* __restrict__ out) {
    int n = blockIdx.x;
    int tid = threadIdx.x;
    __shared__ float f_s[FP];

    const float* rel = g_rel + n * GT;
    float s = fp_b0[tid];
#pragma unroll 4
    for (int h = 0; h < GT; h++)
        s = fmaf(rel[h], fp_w0[h * FP + tid], s);
    f_s[tid] = fmaxf(s, 0.0f);
    __syncthreads();

    if (tid < ASZ) {
        float s2 = fp_b1[tid];
#pragma unroll 4
        for (int h = 0; h < FP; h++)
            s2 = fmaf(f_s[h], fp_w1[h * ASZ + tid], s2);
        out[n * ASZ + tid] = s2;
    }
}

// ---------------- launch ----------------
extern "C" void kernel_launch(void* const* d_in, const int* in_sizes, int n_in,
                              void* d_out, int out_size) {
    const float* image  = (const float*)d_in[0];
    const float* code   = (const float*)d_in[1];
    const float* conv_w = (const float*)d_in[2];
    const float* conv_b = (const float*)d_in[3];
    const float* hp_w0  = (const float*)d_in[4];
    const float* hp_b0  = (const float*)d_in[5];
    const float* hp_w1  = (const float*)d_in[6];
    const float* hp_b1  = (const float*)d_in[7];
    const float* gt_w0  = (const float*)d_in[8];
    const float* gt_b0  = (const float*)d_in[9];
    const float* gt_w1  = (const float*)d_in[10];
    const float* gt_b1  = (const float*)d_in[11];
    const float* fp_w0  = (const float*)d_in[12];
    const float* fp_b0  = (const float*)d_in[13];
    const float* fp_w1  = (const float*)d_in[14];
    const float* fp_b1  = (const float*)d_in[15];
    float* out = (float*)d_out;

    cudaFuncSetAttribute(k_conv_mma, cudaFuncAttributeMaxDynamicSharedMemorySize, 164864);
    cudaFuncSetAttribute(k_hpsi_mma, cudaFuncAttributeMaxDynamicSharedMemorySize, 132096);
    cudaFuncSetAttribute(k_gt_mma,   cudaFuncAttributeMaxDynamicSharedMemorySize, 197632);

    k_prep_all<<<PREP_BLOCKS, 256>>>(image, conv_w, code, hp_w0, hp_b0, gt_w0, gt_b0, gt_w1);
    k_conv_mma<<<NB * 2, 512, 164864>>>(conv_b);
    k_hpsi_mma<<<196, 512, 132096>>>(hp_w1, hp_b1);
    k_softsel<<<NB, 256>>>(gt_w0);
    k_gt_mma<<<196, 512, 197632>>>(gt_b1);
    k_fphi<<<NB, 256>>>(fp_w0, fp_b0, fp_w1, fp_b1, out);
}

// round 12
// speedup vs baseline: 1.1006x; 1.1006x over previous
#include <cuda_runtime.h>
#include <cuda_bf16.h>
#include <cstdint>

// ---------------- problem constants ----------------
#define NB    128
#define CIN   1024
#define HH    14
#define WW    14
#define OO    196
#define CF    128
#define TH    128
#define QD    258
#define CED   130
#define PD    388
#define HP    256
#define GT    256
#define FP    256
#define ASZ   32

// ---------------- scratch ----------------
__device__ __align__(16) __nv_bfloat16 g_imh[NB * 256 * CIN];
__device__ __align__(16) __nv_bfloat16 g_iml[NB * 256 * CIN];
__device__ __align__(16) uint8_t g_wbh[144 * 16384];
__device__ __align__(16) uint8_t g_wbl[144 * 16384];
__device__ __align__(16) float g_xt[NB * OO * CF];
__device__ __align__(16) __nv_bfloat16 g_xth[NB * OO * CF];
__device__ __align__(16) __nv_bfloat16 g_xtl[NB * OO * CF];
__device__ __align__(16) uint8_t g_hpBh[4 * 16384],  g_hpBl[4 * 16384];
__device__ __align__(16) uint8_t g_gt0Bh[4 * 16384], g_gt0Bl[4 * 16384];
__device__ __align__(16) uint8_t g_gt1Bh[8 * 16384], g_gt1Bl[8 * 16384];
__device__ float g_pero_hp[OO * 256], g_pern_hp[NB * 256];
__device__ float g_pero_gt[OO * 256], g_pern_gt[NB * 256];
__device__ float g_att[NB * OO];
__device__ float g_sel[NB * CED];
__device__ float g_rel[NB * GT];

__device__ __forceinline__ float xcoord(int o) { return -1.0f + 2.0f * (float)(o / WW) / 13.0f; }
__device__ __forceinline__ float ycoord(int o) { return -1.0f + 2.0f * (float)(o % WW) / 13.0f; }

// ---------------- helpers ----------------
#define SWZ(x) ((x) ^ (((x) >> 3) & 0x70))

__device__ __forceinline__ uint32_t smem_u32(const void* p) {
    uint32_t a;
    asm("{ .reg .u64 t; cvta.to.shared.u64 t, %1; cvt.u32.u64 %0, t; }" : "=r"(a) : "l"(p));
    return a;
}
__device__ __forceinline__ void ldsm_x4(uint32_t* r, uint32_t addr) {
    asm volatile("ldmatrix.sync.aligned.m8n8.x4.shared.b16 {%0,%1,%2,%3}, [%4];"
                 : "=r"(r[0]), "=r"(r[1]), "=r"(r[2]), "=r"(r[3]) : "r"(addr));
}
__device__ __forceinline__ void mma16816(float* c, const uint32_t* a, uint32_t b0, uint32_t b1) {
    asm volatile("mma.sync.aligned.m16n8k16.row.col.f32.bf16.bf16.f32 "
                 "{%0,%1,%2,%3}, {%4,%5,%6,%7}, {%8,%9}, {%0,%1,%2,%3};"
                 : "+f"(c[0]), "+f"(c[1]), "+f"(c[2]), "+f"(c[3])
                 : "r"(a[0]), "r"(a[1]), "r"(a[2]), "r"(a[3]), "r"(b0), "r"(b1));
}
__device__ __forceinline__ void cp16(uint32_t dst, const void* src) {
    asm volatile("cp.async.cg.shared.global [%0], [%1], 16;" :: "r"(dst), "l"(src));
}
__device__ __forceinline__ void cp_commit() { asm volatile("cp.async.commit_group;" ::: "memory"); }
__device__ __forceinline__ void bf16split(float v, __nv_bfloat16& h, __nv_bfloat16& l) {
    h = __float2bfloat16(v);
    l = __float2bfloat16(v - __bfloat162float(h));
}

// ---------------- mega prep kernel ----------------
#define PREP_BLOCKS 27460

__device__ __forceinline__ void mlppack_one(const float* __restrict__ src,
                                            uint8_t* __restrict__ dstH,
                                            uint8_t* __restrict__ dstL, int idx) {
    int k6    = idx & 63;
    int ch    = (idx >> 6) & 127;
    int chblk = (idx >> 13) & 1;
    int kblk  = idx >> 14;
    float v = src[(kblk * 64 + k6) * 256 + chblk * 128 + ch];
    __nv_bfloat16 hi, lo; bf16split(v, hi, lo);
    int off = (kblk * 2 + chblk) * 16384 + SWZ(ch * 128 + k6 * 2);
    *(__nv_bfloat16*)(dstH + off) = hi;
    *(__nv_bfloat16*)(dstL + off) = lo;
}

__global__ void __launch_bounds__(256) k_prep_all(
    const float* __restrict__ image, const float* __restrict__ conv_w,
    const float* __restrict__ code,
    const float* __restrict__ hp_w0, const float* __restrict__ hp_b0,
    const float* __restrict__ gt_w0, const float* __restrict__ gt_b0,
    const float* __restrict__ gt_w1)
{
    int b = blockIdx.x, tid = threadIdx.x;

    if (b < 4608) {                       // conv weight pack
        int idx = b * 256 + tid;
        int j    = idx & 63;
        int ch   = (idx >> 6) & 127;
        int cb   = (idx >> 13) & 15;
        int kykx = idx >> 17;
        int cin  = cb * 64 + j;
        float v = conv_w[ch * (CIN * 9) + cin * 9 + kykx];
        __nv_bfloat16 hi, lo; bf16split(v, hi, lo);
        int dst = (kykx * 16 + cb) * 16384 + SWZ(ch * 128 + j * 2);
        *(__nv_bfloat16*)(g_wbh + dst) = hi;
        *(__nv_bfloat16*)(g_wbl + dst) = lo;
    } else if (b < 4736) {
        mlppack_one(hp_w0, g_hpBh, g_hpBl, (b - 4608) * 256 + tid);
    } else if (b < 4864) {
        mlppack_one(gt_w0, g_gt0Bh, g_gt0Bl, (b - 4736) * 256 + tid);
    } else if (b < 5120) {
        mlppack_one(gt_w1, g_gt1Bh, g_gt1Bl, (b - 4864) * 256 + tid);
    } else if (b < 12800) {               // halo border zero
        int e = (b - 5120) * 256 + tid;
        int arr = e >= 983040;
        int j = e - arr * 983040;
        int n  = j / (60 * 128);
        int r  = j - n * (60 * 128);
        int bp = r >> 7, u = r & 127;
        int hp;
        if (bp < 16)      hp = bp;
        else if (bp < 32) hp = 240 + (bp - 16);
        else { int i = bp - 32; int hr = 1 + (i >> 1); int hc = (i & 1) ? 15 : 0; hp = hr * 16 + hc; }
        uint4 z = {0, 0, 0, 0};
        size_t o4 = (size_t)(n * 256 + hp) * 128 + u;
        if (arr) ((uint4*)g_iml)[o4] = z; else ((uint4*)g_imh)[o4] = z;
    } else if (b < 27136) {               // image transpose + split
        int bb = b - 12800;
        int pb = bb % 7, cbk = (bb / 7) % 16, n = bb / 112;
        __shared__ float t[64][33];
        int pos0 = pb * 32;
        for (int e = tid; e < 64 * 32; e += 256) {
            int ci = e >> 5, p = e & 31;
            int pos = pos0 + p;
            float v = 0.0f;
            if (pos < OO) v = image[((size_t)n * CIN + cbk * 64 + ci) * OO + pos];
            t[ci][p] = v;
        }
        __syncthreads();
        for (int e = tid; e < 64 * 32; e += 256) {
            int p = e >> 6, ci = e & 63;
            int pos = pos0 + p;
            if (pos < OO) {
                int row = pos / 14, col = pos - row * 14;
                int hp  = (row + 1) * 16 + (col + 1);
                size_t off = ((size_t)n * 256 + hp) * 1024 + cbk * 64 + ci;
                __nv_bfloat16 hi, lo; bf16split(t[ci][p], hi, lo);
                g_imh[off] = hi;
                g_iml[off] = lo;
            }
        }
    } else if (b < 27332) {               // per-o tables
        int o = b - 27136, ch = tid;
        float xc = xcoord(o), yc = ycoord(o);
        g_pero_hp[o * 256 + ch] = xc * hp_w0[128 * 256 + ch] + yc * hp_w0[129 * 256 + ch];
        g_pero_gt[o * 256 + ch] = xc * gt_w0[128 * 256 + ch] + yc * gt_w0[129 * 256 + ch];
    } else {                              // per-n tables + zero rel
        int n = b - 27332, ch = tid;
        float sh = hp_b0[ch], sg = gt_b0[ch];
#pragma unroll 4
        for (int d = 0; d < 128; d++) {
            float c = code[n * 128 + d];
            sh = fmaf(c, hp_w0[(130 + d) * 256 + ch], sh);
            sg = fmaf(c, gt_w0[(130 + d) * 256 + ch], sg);
        }
        g_pern_hp[n * 256 + ch] = sh;
        g_pern_gt[n * 256 + ch] = sg;
        g_rel[n * 256 + ch] = 0.0f;
    }
}

// ---------------- conv: mma.sync bf16 3-section split GEMM, M=208 (round-9 config) ----------------
__device__ __forceinline__ void prefetch_B3(int g, uint32_t Bb, int tid) {
    int cb = g / 9, kykx = g - cb * 9;
    size_t off = (size_t)(kykx * 16 + cb) * 16384;
    uint32_t dst = Bb + (uint32_t)(g % 3) * 32768;
#pragma unroll
    for (int t = 0; t < 2; t++) {
        int i = tid + t * 512;
        cp16(dst + i * 16,         g_wbh + off + i * 16);
        cp16(dst + 16384 + i * 16, g_wbl + off + i * 16);
    }
}

template<int NMF>
__device__ __forceinline__ void conv_stage(uint32_t haloH, uint32_t haloL, uint32_t Bstage,
                                           int kd, const int* pbA, int chB0, int kHi,
                                           float (*acc)[16]) {
    uint32_t Bh = Bstage, Bl = Bstage + 16384;
#pragma unroll
    for (int ks = 0; ks < 4; ks++) {
        uint32_t bh[2][4], bl[2][4], a[NMF][4];
        uint32_t kof = (uint32_t)(ks * 32 + kHi);
#pragma unroll
        for (int bf = 0; bf < 2; bf++) ldsm_x4(bh[bf], Bh + SWZ((uint32_t)((chB0 + bf * 16) * 128) + kof));
#pragma unroll
        for (int mf = 0; mf < NMF; mf++) ldsm_x4(a[mf], haloH + SWZ((uint32_t)((pbA[mf] + kd) * 128) + kof));
#pragma unroll
        for (int mf = 0; mf < NMF; mf++)
#pragma unroll
            for (int nf = 0; nf < 4; nf++)
                mma16816(&acc[mf][nf * 4], a[mf], bh[nf >> 1][nf & 1], bh[nf >> 1][(nf & 1) + 2]);
#pragma unroll
        for (int bf = 0; bf < 2; bf++) ldsm_x4(bl[bf], Bl + SWZ((uint32_t)((chB0 + bf * 16) * 128) + kof));
#pragma unroll
        for (int mf = 0; mf < NMF; mf++)
#pragma unroll
            for (int nf = 0; nf < 4; nf++)
                mma16816(&acc[mf][nf * 4], a[mf], bl[nf >> 1][nf & 1], bl[nf >> 1][(nf & 1) + 2]);
#pragma unroll
        for (int mf = 0; mf < NMF; mf++) ldsm_x4(a[mf], haloL + SWZ((uint32_t)((pbA[mf] + kd) * 128) + kof));
#pragma unroll
        for (int mf = 0; mf < NMF; mf++)
#pragma unroll
            for (int nf = 0; nf < 4; nf++)
                mma16816(&acc[mf][nf * 4], a[mf], bh[nf >> 1][nf & 1], bh[nf >> 1][(nf & 1) + 2]);
    }
}

__global__ void __launch_bounds__(512) k_conv_mma(const float* __restrict__ conv_b) {
    extern __shared__ char sm_raw[];
    __shared__ float s_bias[128];
    const int tid = threadIdx.x, n = blockIdx.x;
    const int wid = tid >> 5, lane = tid & 31;
    const int wm = wid >> 2, wn = wid & 3;            // SMSP = wn; {4,3,3,3} mf per SMSP
    const int nmf  = (wm == 0) ? 4 : 3;
    const int rowb = (wm == 0) ? 0 : 16 + wm * 48;    // 0, 64, 112, 160

    uint32_t raw = smem_u32(sm_raw);
    uint32_t base = (raw + 1023u) & ~1023u;
    char* sm = sm_raw + (base - raw);
    const uint32_t haloH = base, haloL = base + 32768, Bb = base + 65536;

    if (tid < 128) s_bias[tid] = conv_b[tid];

    float acc[4][16];
#pragma unroll
    for (int i = 0; i < 4; i++)
#pragma unroll
        for (int j = 0; j < 16; j++) acc[i][j] = 0.0f;

    int pbA[4];
#pragma unroll
    for (int mf = 0; mf < 4; mf++) {
        int o = rowb + mf * 16 + (lane & 15);
        if (o > 195) o = 195;
        int row = o / 14, col = o - row * 14;
        pbA[mf] = row * 16 + col;
    }
    const int kHi = (lane >> 4) * 16;
    const int chB0 = wn * 32 + (lane & 15);

    prefetch_B3(0, Bb, tid); cp_commit();
    prefetch_B3(1, Bb, tid); cp_commit();

    for (int gs = 0; gs < 144; gs++) {
        int cb = gs / 9, kykx = gs - cb * 9;
        if (kykx == 0) {
            __syncthreads();
#pragma unroll
            for (int t = 0; t < 8; t++) {
                int idx = tid + t * 512;
                int half = idx >> 11;
                int j = idx & 2047;
                int p = j >> 3, u = j & 7;
                const __nv_bfloat16* srcp = (half ? g_iml : g_imh) + ((size_t)n * 256 + p) * 1024 + cb * 64;
                uint4 v = ((const uint4*)srcp)[u];
                *(uint4*)(sm + half * 32768 + SWZ(p * 128 + u * 16)) = v;
            }
        }
        if (gs < 143) asm volatile("cp.async.wait_group 1;" ::: "memory");
        else          asm volatile("cp.async.wait_group 0;" ::: "memory");
        __syncthreads();
        if (gs + 2 < 144) { prefetch_B3(gs + 2, Bb, tid); cp_commit(); }

        int ky = kykx / 3, kx = kykx - ky * 3;
        int kd = ky * 16 + kx;
        uint32_t Bst = Bb + (uint32_t)(gs % 3) * 32768;

        if (wm == 0) conv_stage<4>(haloH, haloL, Bst, kd, pbA, chB0, kHi, acc);
        else         conv_stage<3>(haloH, haloL, Bst, kd, pbA, chB0, kHi, acc);
    }

    int g = lane >> 2, t2 = (lane & 3) * 2;
    float* dst = g_xt + (size_t)n * OO * CF;
#pragma unroll
    for (int mf = 0; mf < 4; mf++) {
        if (mf < nmf) {
#pragma unroll
            for (int nf = 0; nf < 4; nf++) {
                int ch = wn * 32 + nf * 8 + t2;
                float b0 = s_bias[ch], b1 = s_bias[ch + 1];
#pragma unroll
                for (int h = 0; h < 2; h++) {
                    int o = rowb + mf * 16 + g + h * 8;
                    if (o < OO) {
                        float v0 = acc[mf][nf * 4 + h * 2 + 0] + b0;
                        float v1 = acc[mf][nf * 4 + h * 2 + 1] + b1;
                        size_t r = (size_t)n * OO + o;
                        dst[(size_t)o * CF + ch]     = v0;
                        dst[(size_t)o * CF + ch + 1] = v1;
                        __nv_bfloat16 h0, l0, h1, l1;
                        bf16split(v0, h0, l0);
                        bf16split(v1, h1, l1);
                        *(__nv_bfloat162*)(g_xth + r * CF + ch) = __nv_bfloat162{h0, h1};
                        *(__nv_bfloat162*)(g_xtl + r * CF + ch) = __nv_bfloat162{l0, l1};
                    }
                }
            }
        }
    }
}

// ---------------- generic GEMM stage (M=128, 16 warps as 2M x 8N) ----------------
__device__ __forceinline__ void gemm_stage(float (*acc)[16], uint32_t AhT, uint32_t AlT,
                                           uint32_t Bt, bool doLo,
                                           const uint32_t* rbase, uint32_t chbase, uint32_t kHi) {
#pragma unroll
    for (int ks = 0; ks < 4; ks++) {
        uint32_t b[2][4];
        ldsm_x4(b[0], Bt + SWZ(chbase + ks * 32 + kHi));
        ldsm_x4(b[1], Bt + SWZ(chbase + 16 * 128 + ks * 32 + kHi));
#pragma unroll
        for (int mf = 0; mf < 4; mf++) {
            uint32_t a[4];
            ldsm_x4(a, AhT + SWZ(rbase[mf] + ks * 32 + kHi));
#pragma unroll
            for (int nf = 0; nf < 4; nf++)
                mma16816(&acc[mf][nf * 4], a,
                         (nf & 1) ? b[nf >> 1][1] : b[nf >> 1][0],
                         (nf & 1) ? b[nf >> 1][3] : b[nf >> 1][2]);
            if (doLo) {
                uint32_t al[4];
                ldsm_x4(al, AlT + SWZ(rbase[mf] + ks * 32 + kHi));
#pragma unroll
                for (int nf = 0; nf < 4; nf++)
                    mma16816(&acc[mf][nf * 4], al,
                             (nf & 1) ? b[nf >> 1][1] : b[nf >> 1][0],
                             (nf & 1) ? b[nf >> 1][3] : b[nf >> 1][2]);
            }
        }
    }
}

__device__ __forceinline__ void load_A_tile(uint32_t smb, int r0, int tid) {
#pragma unroll
    for (int t = 0; t < 8; t++) {
        int idx = tid + t * 512;
        int half = idx >> 11;
        int j = idx & 2047;
        int row = j >> 4, cc = j & 15;
        int kblk = cc >> 3, u = cc & 7;
        const __nv_bfloat16* src = (half ? g_xtl : g_xth) + (size_t)(r0 + row) * 128 + kblk * 64 + u * 8;
        cp16(smb + half * 32768 + kblk * 16384 + SWZ(row * 128 + u * 16), src);
    }
}

// ---------------- h_psi as GEMM (196 M-tiles) ----------------
__global__ void __launch_bounds__(512) k_hpsi_mma(const float* __restrict__ hp_w1,
                                                  const float* __restrict__ hp_b1) {
    extern __shared__ char sm_raw[];
    __shared__ float s_w1[256];
    __shared__ float attp[8][128];

    const int tid = threadIdx.x;
    const int r0 = blockIdx.x * 128;
    const int wid = tid >> 5, lane = tid & 31;
    const int wm = wid & 1, wn = wid >> 1;

    uint32_t raw = smem_u32(sm_raw);
    uint32_t smb = (raw + 1023u) & ~1023u;
    const uint32_t Bbuf = smb + 65536;

    if (tid < 256) s_w1[tid] = hp_w1[tid];

    uint32_t rbase[4];
#pragma unroll
    for (int mf = 0; mf < 4; mf++) rbase[mf] = (uint32_t)(wm * 64 + mf * 16 + (lane & 15)) * 128;
    const uint32_t kHi = (lane >> 4) * 16;
    const uint32_t chbase = (uint32_t)((wn & 3) * 32 + (lane & 15)) * 128;
    const uint32_t Bwn = (wn >> 2) * 16384;

    float acc[4][16];
#pragma unroll
    for (int i = 0; i < 4; i++)
#pragma unroll
        for (int j = 0; j < 16; j++) acc[i][j] = 0.0f;

    {
        const uint8_t* src = g_hpBh;
#pragma unroll
        for (int t = 0; t < 4; t++) cp16(Bbuf + (tid + t * 512) * 16, src + (tid + t * 512) * 16);
        load_A_tile(smb, r0, tid);
        cp_commit();
    }

    for (int s = 0; s < 4; s++) {
        if (s < 3) {
            int sn = s + 1;
            const uint8_t* src = ((sn & 1) ? g_hpBl : g_hpBh) + (size_t)(sn >> 1) * 32768;
            uint32_t dstb = Bbuf + (sn & 1) * 32768;
#pragma unroll
            for (int t = 0; t < 4; t++) cp16(dstb + (tid + t * 512) * 16, src + (tid + t * 512) * 16);
            cp_commit();
            asm volatile("cp.async.wait_group 1;" ::: "memory");
        } else {
            asm volatile("cp.async.wait_group 0;" ::: "memory");
        }
        __syncthreads();
        int kblk = s >> 1;
        gemm_stage(acc, smb + kblk * 16384, smb + 32768 + kblk * 16384,
                   Bbuf + (s & 1) * 32768 + Bwn, (s & 1) == 0, rbase, chbase, kHi);
        __syncthreads();
    }

    int g = lane >> 2, t2 = (lane & 3) * 2;
    float psum[4][2];
#pragma unroll
    for (int mf = 0; mf < 4; mf++) { psum[mf][0] = 0.0f; psum[mf][1] = 0.0f; }
#pragma unroll
    for (int mf = 0; mf < 4; mf++)
#pragma unroll
        for (int h = 0; h < 2; h++) {
            int row = wm * 64 + mf * 16 + g + h * 8;
            int r = r0 + row;
            int n = r / OO, o = r - n * OO;
#pragma unroll
            for (int nf = 0; nf < 4; nf++)
#pragma unroll
                for (int j = 0; j < 2; j++) {
                    int ch = wn * 32 + nf * 8 + t2 + j;
                    float v = acc[mf][nf * 4 + h * 2 + j] + g_pero_hp[o * 256 + ch] + g_pern_hp[n * 256 + ch];
                    psum[mf][h] += fmaxf(v, 0.0f) * s_w1[ch];
                }
        }
#pragma unroll
    for (int mf = 0; mf < 4; mf++)
#pragma unroll
        for (int h = 0; h < 2; h++) {
            float p = psum[mf][h];
            p += __shfl_xor_sync(0xffffffffu, p, 1);
            p += __shfl_xor_sync(0xffffffffu, p, 2);
            if ((lane & 3) == 0) attp[wn][wm * 64 + mf * 16 + g + h * 8] = p;
        }
    __syncthreads();
    if (tid < 128) {
        float a = hp_b1[0];
#pragma unroll
        for (int w = 0; w < 8; w++) a += attp[w][tid];
        g_att[r0 + tid] = a;
    }
}

// ---------------- fused g_theta (layer1 + layer2 + object-sum) ----------------
__global__ void __launch_bounds__(512) k_gt_mma(const float* __restrict__ gt_b1) {
    extern __shared__ char sm_raw[];
    __shared__ float s_b1[256];
    __shared__ float relp[2][256];

    const int tid = threadIdx.x;
    const int r0 = blockIdx.x * 128;
    const int wid = tid >> 5, lane = tid & 31;
    const int wm = wid & 1, wn = wid >> 1;

    uint32_t raw = smem_u32(sm_raw);
    uint32_t smb = (raw + 1023u) & ~1023u;
    const uint32_t Bbuf = smb + 131072;

    if (tid < 256) s_b1[tid] = gt_b1[tid];
    if (tid < 512) ((float*)relp)[tid] = 0.0f;

    uint32_t rbase[4];
#pragma unroll
    for (int mf = 0; mf < 4; mf++) rbase[mf] = (uint32_t)(wm * 64 + mf * 16 + (lane & 15)) * 128;
    const uint32_t kHi = (lane >> 4) * 16;
    const uint32_t chbase = (uint32_t)((wn & 3) * 32 + (lane & 15)) * 128;
    const uint32_t Bwn = (wn >> 2) * 16384;
    const int g = lane >> 2, t2 = (lane & 3) * 2;

    float acc[4][16];
#pragma unroll
    for (int i = 0; i < 4; i++)
#pragma unroll
        for (int j = 0; j < 16; j++) acc[i][j] = 0.0f;

    {
#pragma unroll
        for (int t = 0; t < 4; t++) cp16(Bbuf + (tid + t * 512) * 16, g_gt0Bh + (tid + t * 512) * 16);
        load_A_tile(smb, r0, tid);
        cp_commit();
    }

    for (int s = 0; s < 12; s++) {
        if (s < 11) {
            int sn = s + 1;
            const uint8_t* basep;
            int kblk;
            if (sn < 4) { basep = (sn & 1) ? g_gt0Bl : g_gt0Bh; kblk = sn >> 1; }
            else        { int t = sn - 4; basep = (t & 1) ? g_gt1Bl : g_gt1Bh; kblk = t >> 1; }
            const uint8_t* src = basep + (size_t)kblk * 32768;
            uint32_t dstb = Bbuf + (sn & 1) * 32768;
#pragma unroll
            for (int t = 0; t < 4; t++) cp16(dstb + (tid + t * 512) * 16, src + (tid + t * 512) * 16);
            cp_commit();
            asm volatile("cp.async.wait_group 1;" ::: "memory");
        } else {
            asm volatile("cp.async.wait_group 0;" ::: "memory");
        }
        __syncthreads();

        if (s < 4) {
            int kblk = s >> 1;
            gemm_stage(acc, smb + kblk * 16384, smb + 32768 + kblk * 16384,
                       Bbuf + (s & 1) * 32768 + Bwn, (s & 1) == 0, rbase, chbase, kHi);
        } else {
            int kt = (s - 4) >> 1;
            gemm_stage(acc, smb + kt * 16384, smb + 65536 + kt * 16384,
                       Bbuf + (s & 1) * 32768 + Bwn, (s & 1) == 0, rbase, chbase, kHi);
        }
        __syncthreads();

        if (s == 3) {
#pragma unroll
            for (int mf = 0; mf < 4; mf++)
#pragma unroll
                for (int h = 0; h < 2; h++) {
                    int row = wm * 64 + mf * 16 + g + h * 8;
                    int r = r0 + row;
                    int n = r / OO, o = r - n * OO;
#pragma unroll
                    for (int nf = 0; nf < 4; nf++) {
                        int ch0 = wn * 32 + nf * 8 + t2;
                        float v0 = acc[mf][nf * 4 + h * 2 + 0] + g_pero_gt[o * 256 + ch0]     + g_pern_gt[n * 256 + ch0];
                        float v1 = acc[mf][nf * 4 + h * 2 + 1] + g_pero_gt[o * 256 + ch0 + 1] + g_pern_gt[n * 256 + ch0 + 1];
                        v0 = fmaxf(v0, 0.0f); v1 = fmaxf(v1, 0.0f);
                        __nv_bfloat16 h0, l0, h1, l1;
                        bf16split(v0, h0, l0);
                        bf16split(v1, h1, l1);
                        uint32_t off = (uint32_t)(ch0 >> 6) * 16384 + SWZ(row * 128 + (ch0 & 63) * 2);
                        *(__nv_bfloat162*)(sm_raw + (smb - raw) + off)         = __nv_bfloat162{h0, h1};
                        *(__nv_bfloat162*)(sm_raw + (smb - raw) + 65536 + off) = __nv_bfloat162{l0, l1};
                    }
                }
#pragma unroll
            for (int i = 0; i < 4; i++)
#pragma unroll
                for (int j = 0; j < 16; j++) acc[i][j] = 0.0f;
            __syncthreads();
        }
    }

    const int n0 = r0 / OO;
    const int n1 = (r0 + 127) / OO;
#pragma unroll
    for (int mf = 0; mf < 4; mf++)
#pragma unroll
        for (int h = 0; h < 2; h++) {
            int row = wm * 64 + mf * 16 + g + h * 8;
            int r = r0 + row;
            int n = r / OO;
            int nn = (n != n0);
#pragma unroll
            for (int nf = 0; nf < 4; nf++)
#pragma unroll
                for (int j = 0; j < 2; j++) {
                    int ch = wn * 32 + nf * 8 + t2 + j;
                    float v = fmaxf(acc[mf][nf * 4 + h * 2 + j] + s_b1[ch], 0.0f);
                    atomicAdd(&relp[nn][ch], v);
                }
        }
    __syncthreads();
    if (tid < 256) {
        atomicAdd(&g_rel[n0 * 256 + tid], relp[0][tid]);
    } else {
        int ch = tid - 256;
        if (n1 != n0) atomicAdd(&g_rel[n1 * 256 + ch], relp[1][ch]);
    }
}

// ---------------- softmax + soft selection + pern_gt finish (512 threads) ----------------
__global__ void __launch_bounds__(512) k_softsel(const float* __restrict__ gt_w0) {
    int n = blockIdx.x;
    int tid = threadIdx.x;
    __shared__ float att_s[OO];
    __shared__ float red_s[16];
    __shared__ float selp[4][128];
    __shared__ float sel_s[CED];
    __shared__ float pgp[2][256];

    if (tid < OO) att_s[tid] = g_att[n * OO + tid];
    __syncthreads();

    float v = (tid < OO) ? att_s[tid] : -1e30f;
#pragma unroll
    for (int off = 16; off > 0; off >>= 1) v = fmaxf(v, __shfl_xor_sync(0xffffffffu, v, off));
    if ((tid & 31) == 0) red_s[tid >> 5] = v;
    __syncthreads();
    float m = -1e30f;
#pragma unroll
    for (int i = 0; i < 16; i++) m = fmaxf(m, red_s[i]);
    __syncthreads();

    float e = (tid < OO) ? expf(att_s[tid] - m) : 0.0f;
    float sv = e;
#pragma unroll
    for (int off = 16; off > 0; off >>= 1) sv += __shfl_xor_sync(0xffffffffu, sv, off);
    if ((tid & 31) == 0) red_s[tid >> 5] = sv;
    __syncthreads();
    float tot = 0.0f;
#pragma unroll
    for (int i = 0; i < 16; i++) tot += red_s[i];
    if (tid < OO) att_s[tid] = e / tot;
    __syncthreads();

    // selected: quarter q owns 49 objects, thread owns d; 8 accumulators
    {
        const float* xtn = g_xt + (size_t)n * OO * CF;
        int q = tid >> 7, d = tid & 127;
        int o0 = q * 49;
        float a[8];
#pragma unroll
        for (int k = 0; k < 8; k++) a[k] = 0.0f;
#pragma unroll
        for (int i = 0; i < 48; i += 8) {
#pragma unroll
            for (int k = 0; k < 8; k++)
                a[k] = fmaf(att_s[o0 + i + k], xtn[(size_t)(o0 + i + k) * CF + d], a[k]);
        }
        a[0] = fmaf(att_s[o0 + 48], xtn[(size_t)(o0 + 48) * CF + d], a[0]);
        selp[q][d] = ((a[0] + a[1]) + (a[2] + a[3])) + ((a[4] + a[5]) + (a[6] + a[7]));
    }
    __syncthreads();
    if (tid < 128) {
        float s = (selp[0][tid] + selp[1][tid]) + (selp[2][tid] + selp[3][tid]);
        g_sel[n * CED + tid] = s;
        sel_s[tid] = s;
    } else if (tid == 128) {
        float a = 0.0f;
        for (int o = 0; o < OO; o++) a = fmaf(att_s[o], xcoord(o), a);
        g_sel[n * CED + 128] = a;
        sel_s[128] = a;
    } else if (tid == 129) {
        float a = 0.0f;
        for (int o = 0; o < OO; o++) a = fmaf(att_s[o], ycoord(o), a);
        g_sel[n * CED + 129] = a;
        sel_s[129] = a;
    }
    __syncthreads();

    // finish pern_gt: sel . gt_w0[258:388], split 2-way over d
    {
        int p = tid >> 8, ch = tid & 255;
        int d0 = p * 65, d1 = d0 + 65;
        float s = 0.0f;
#pragma unroll 4
        for (int d = d0; d < d1; d++)
            s = fmaf(sel_s[d], gt_w0[(QD + d) * 256 + ch], s);
        pgp[p][ch] = s;
    }
    __syncthreads();
    if (tid < 256)
        g_pern_gt[n * 256 + tid] += pgp[0][tid] + pgp[1][tid];
}

// ---------------- f_phi head ----------------
__global__ void __launch_bounds__(256) k_fphi(const float* __restrict__ fp_w0,
                                              const float* __restrict__ fp_b0,
                                              const float* __restrict__ fp_w1,
                                              const float* __restrict__ fp_b1,
                                              float* __restrict__ out) {
    int n = blockIdx.x;
    int tid = threadIdx.x;
    __shared__ float f_s[FP];

    const float* rel = g_rel + n * GT;
    float s = fp_b0[tid];
#pragma unroll 4
    for (int h = 0; h < GT; h++)
        s = fmaf(rel[h], fp_w0[h * FP + tid], s);
    f_s[tid] = fmaxf(s, 0.0f);
    __syncthreads();

    if (tid < ASZ) {
        float s2 = fp_b1[tid];
#pragma unroll 4
        for (int h = 0; h < FP; h++)
            s2 = fmaf(f_s[h], fp_w1[h * ASZ + tid], s2);
        out[n * ASZ + tid] = s2;
    }
}

// ---------------- launch ----------------
extern "C" void kernel_launch(void* const* d_in, const int* in_sizes, int n_in,
                              void* d_out, int out_size) {
    const float* image  = (const float*)d_in[0];
    const float* code   = (const float*)d_in[1];
    const float* conv_w = (const float*)d_in[2];
    const float* conv_b = (const float*)d_in[3];
    const float* hp_w0  = (const float*)d_in[4];
    const float* hp_b0  = (const float*)d_in[5];
    const float* hp_w1  = (const float*)d_in[6];
    const float* hp_b1  = (const float*)d_in[7];
    const float* gt_w0  = (const float*)d_in[8];
    const float* gt_b0  = (const float*)d_in[9];
    const float* gt_w1  = (const float*)d_in[10];
    const float* gt_b1  = (const float*)d_in[11];
    const float* fp_w0  = (const float*)d_in[12];
    const float* fp_b0  = (const float*)d_in[13];
    const float* fp_w1  = (const float*)d_in[14];
    const float* fp_b1  = (const float*)d_in[15];
    float* out = (float*)d_out;

    cudaFuncSetAttribute(k_conv_mma, cudaFuncAttributeMaxDynamicSharedMemorySize, 164864);
    cudaFuncSetAttribute(k_hpsi_mma, cudaFuncAttributeMaxDynamicSharedMemorySize, 132096);
    cudaFuncSetAttribute(k_gt_mma,   cudaFuncAttributeMaxDynamicSharedMemorySize, 197632);

    k_prep_all<<<PREP_BLOCKS, 256>>>(image, conv_w, code, hp_w0, hp_b0, gt_w0, gt_b0, gt_w1);
    k_conv_mma<<<NB, 512, 164864>>>(conv_b);
    k_hpsi_mma<<<196, 512, 132096>>>(hp_w1, hp_b1);
    k_softsel<<<NB, 512>>>(gt_w0);
    k_gt_mma<<<196, 512, 197632>>>(gt_b1);
    k_fphi<<<NB, 256>>>(fp_w0, fp_b0, fp_w1, fp_b1, out);
}

// round 14
// speedup vs baseline: 1.1900x; 1.0813x over previous
#include <cuda_runtime.h>
#include <cuda_bf16.h>
#include <cstdint>

// ---------------- problem constants ----------------
#define NB    128
#define CIN   1024
#define HH    14
#define WW    14
#define OO    196
#define CF    128
#define TH    128
#define QD    258
#define CED   130
#define PD    388
#define HP    256
#define GT    256
#define FP    256
#define ASZ   32

// ---------------- scratch ----------------
// NOTE: g_imh/g_iml halo borders rely on CUDA zero-initialization of __device__
// globals; k_prep_all writes interior cells only, nothing ever writes borders.
__device__ __align__(16) __nv_bfloat16 g_imh[NB * 256 * CIN];
__device__ __align__(16) __nv_bfloat16 g_iml[NB * 256 * CIN];
__device__ __align__(16) uint8_t g_wbh[144 * 16384];
__device__ __align__(16) uint8_t g_wbl[144 * 16384];
__device__ __align__(16) float g_xt[NB * OO * CF];
__device__ __align__(16) __nv_bfloat16 g_xth[NB * OO * CF];
__device__ __align__(16) __nv_bfloat16 g_xtl[NB * OO * CF];
__device__ __align__(16) uint8_t g_hpBh[4 * 16384],  g_hpBl[4 * 16384];
__device__ __align__(16) uint8_t g_gt0Bh[4 * 16384], g_gt0Bl[4 * 16384];
__device__ __align__(16) uint8_t g_gt1Bh[8 * 16384], g_gt1Bl[8 * 16384];
__device__ float g_pero_hp[OO * 256], g_pern_hp[NB * 256];
__device__ float g_pero_gt[OO * 256], g_pern_gt[NB * 256];
__device__ float g_att[NB * OO];
__device__ float g_sel[NB * CED];
__device__ float g_rel[NB * GT];

__device__ __forceinline__ float xcoord(int o) { return -1.0f + 2.0f * (float)(o / WW) / 13.0f; }
__device__ __forceinline__ float ycoord(int o) { return -1.0f + 2.0f * (float)(o % WW) / 13.0f; }

// ---------------- helpers ----------------
#define SWZ(x) ((x) ^ (((x) >> 3) & 0x70))

__device__ __forceinline__ uint32_t smem_u32(const void* p) {
    uint32_t a;
    asm("{ .reg .u64 t; cvta.to.shared.u64 t, %1; cvt.u32.u64 %0, t; }" : "=r"(a) : "l"(p));
    return a;
}
__device__ __forceinline__ void ldsm_x4(uint32_t* r, uint32_t addr) {
    asm volatile("ldmatrix.sync.aligned.m8n8.x4.shared.b16 {%0,%1,%2,%3}, [%4];"
                 : "=r"(r[0]), "=r"(r[1]), "=r"(r[2]), "=r"(r[3]) : "r"(addr));
}
__device__ __forceinline__ void mma16816(float* c, const uint32_t* a, uint32_t b0, uint32_t b1) {
    asm volatile("mma.sync.aligned.m16n8k16.row.col.f32.bf16.bf16.f32 "
                 "{%0,%1,%2,%3}, {%4,%5,%6,%7}, {%8,%9}, {%0,%1,%2,%3};"
                 : "+f"(c[0]), "+f"(c[1]), "+f"(c[2]), "+f"(c[3])
                 : "r"(a[0]), "r"(a[1]), "r"(a[2]), "r"(a[3]), "r"(b0), "r"(b1));
}
__device__ __forceinline__ void cp16(uint32_t dst, const void* src) {
    asm volatile("cp.async.cg.shared.global [%0], [%1], 16;" :: "r"(dst), "l"(src));
}
__device__ __forceinline__ void cp_commit() { asm volatile("cp.async.commit_group;" ::: "memory"); }
__device__ __forceinline__ void bf16split(float v, __nv_bfloat16& h, __nv_bfloat16& l) {
    h = __float2bfloat16(v);
    l = __float2bfloat16(v - __bfloat162float(h));
}

// ---------------- mega prep kernel (no border zeroing: zero-init covers it) ----------------
// [0,4608) conv wpack | [4608,4736) hp | [4736,4864) gt0 | [4864,5120) gt1
// [5120,19456) imsplit | [19456,19652) per-o | [19652,19780) per-n + zero rel
#define PREP_BLOCKS 19780

__device__ __forceinline__ void mlppack_one(const float* __restrict__ src,
                                            uint8_t* __restrict__ dstH,
                                            uint8_t* __restrict__ dstL, int idx) {
    int k6    = idx & 63;
    int ch    = (idx >> 6) & 127;
    int chblk = (idx >> 13) & 1;
    int kblk  = idx >> 14;
    float v = src[(kblk * 64 + k6) * 256 + chblk * 128 + ch];
    __nv_bfloat16 hi, lo; bf16split(v, hi, lo);
    int off = (kblk * 2 + chblk) * 16384 + SWZ(ch * 128 + k6 * 2);
    *(__nv_bfloat16*)(dstH + off) = hi;
    *(__nv_bfloat16*)(dstL + off) = lo;
}

__global__ void __launch_bounds__(256) k_prep_all(
    const float* __restrict__ image, const float* __restrict__ conv_w,
    const float* __restrict__ code,
    const float* __restrict__ hp_w0, const float* __restrict__ hp_b0,
    const float* __restrict__ gt_w0, const float* __restrict__ gt_b0,
    const float* __restrict__ gt_w1)
{
    int b = blockIdx.x, tid = threadIdx.x;

    if (b < 4608) {                       // conv weight pack
        int idx = b * 256 + tid;
        int j    = idx & 63;
        int ch   = (idx >> 6) & 127;
        int cb   = (idx >> 13) & 15;
        int kykx = idx >> 17;
        int cin  = cb * 64 + j;
        float v = conv_w[ch * (CIN * 9) + cin * 9 + kykx];
        __nv_bfloat16 hi, lo; bf16split(v, hi, lo);
        int dst = (kykx * 16 + cb) * 16384 + SWZ(ch * 128 + j * 2);
        *(__nv_bfloat16*)(g_wbh + dst) = hi;
        *(__nv_bfloat16*)(g_wbl + dst) = lo;
    } else if (b < 4736) {
        mlppack_one(hp_w0, g_hpBh, g_hpBl, (b - 4608) * 256 + tid);
    } else if (b < 4864) {
        mlppack_one(gt_w0, g_gt0Bh, g_gt0Bl, (b - 4736) * 256 + tid);
    } else if (b < 5120) {
        mlppack_one(gt_w1, g_gt1Bh, g_gt1Bl, (b - 4864) * 256 + tid);
    } else if (b < 19456) {               // image transpose + split
        int bb = b - 5120;
        int pb = bb % 7, cbk = (bb / 7) % 16, n = bb / 112;
        __shared__ float t[64][33];
        int pos0 = pb * 32;
        for (int e = tid; e < 64 * 32; e += 256) {
            int ci = e >> 5, p = e & 31;
            int pos = pos0 + p;
            float v = 0.0f;
            if (pos < OO) v = image[((size_t)n * CIN + cbk * 64 + ci) * OO + pos];
            t[ci][p] = v;
        }
        __syncthreads();
        for (int e = tid; e < 64 * 32; e += 256) {
            int p = e >> 6, ci = e & 63;
            int pos = pos0 + p;
            if (pos < OO) {
                int row = pos / 14, col = pos - row * 14;
                int hp  = (row + 1) * 16 + (col + 1);
                size_t off = ((size_t)n * 256 + hp) * 1024 + cbk * 64 + ci;
                __nv_bfloat16 hi, lo; bf16split(t[ci][p], hi, lo);
                g_imh[off] = hi;
                g_iml[off] = lo;
            }
        }
    } else if (b < 19652) {               // per-o tables
        int o = b - 19456, ch = tid;
        float xc = xcoord(o), yc = ycoord(o);
        g_pero_hp[o * 256 + ch] = xc * hp_w0[128 * 256 + ch] + yc * hp_w0[129 * 256 + ch];
        g_pero_gt[o * 256 + ch] = xc * gt_w0[128 * 256 + ch] + yc * gt_w0[129 * 256 + ch];
    } else {                              // per-n tables + zero rel
        int n = b - 19652, ch = tid;
        float sh = hp_b0[ch], sg = gt_b0[ch];
#pragma unroll 4
        for (int d = 0; d < 128; d++) {
            float c = code[n * 128 + d];
            sh = fmaf(c, hp_w0[(130 + d) * 256 + ch], sh);
            sg = fmaf(c, gt_w0[(130 + d) * 256 + ch], sg);
        }
        g_pern_hp[n * 256 + ch] = sh;
        g_pern_gt[n * 256 + ch] = sg;
        g_rel[n * 256 + ch] = 0.0f;
    }
}

// ---------------- conv: global unit-split, 148 CTAs, one wave ----------------
// 1664 row-units (128 img x 13); CTA i owns units [i*1664/148, (i+1)*1664/148) = 11-12,
// spanning <=2 images. smem: haloA(H32K,L32K) haloB(H32K,L32K) | B 2x32K = 192KB + 1K pad.
#define NUNITS 1664
#define NCTA   148
#define CONV_SMEM 197632   // 192K + 1K alignment slack (base is aligned up to 1024)

__device__ __forceinline__ void prefetch_B2(int g, uint32_t Bb, int tid) {
    int cb = g / 9, kykx = g - cb * 9;
    size_t off = (size_t)(kykx * 16 + cb) * 16384;
    uint32_t dst = Bb + (uint32_t)(g & 1) * 32768;
#pragma unroll
    for (int t = 0; t < 2; t++) {
        int i = tid + t * 512;
        cp16(dst + i * 16,         g_wbh + off + i * 16);
        cp16(dst + 16384 + i * 16, g_wbl + off + i * 16);
    }
}

template<int NMF>
__device__ __forceinline__ void conv_stage(const uint32_t* aHb, uint32_t Bstage,
                                           int kd, const int* pbA, int chB0, int kHi,
                                           float (*acc)[16]) {
    uint32_t Bh = Bstage, Bl = Bstage + 16384;
#pragma unroll
    for (int ks = 0; ks < 4; ks++) {
        uint32_t bh[2][4], bl[2][4], a[NMF][4];
        uint32_t kof = (uint32_t)(ks * 32 + kHi);
#pragma unroll
        for (int bf = 0; bf < 2; bf++) ldsm_x4(bh[bf], Bh + SWZ((uint32_t)((chB0 + bf * 16) * 128) + kof));
#pragma unroll
        for (int mf = 0; mf < NMF; mf++) ldsm_x4(a[mf], aHb[mf] + SWZ((uint32_t)((pbA[mf] + kd) * 128) + kof));
#pragma unroll
        for (int mf = 0; mf < NMF; mf++)
#pragma unroll
            for (int nf = 0; nf < 4; nf++)
                mma16816(&acc[mf][nf * 4], a[mf], bh[nf >> 1][nf & 1], bh[nf >> 1][(nf & 1) + 2]);
#pragma unroll
        for (int bf = 0; bf < 2; bf++) ldsm_x4(bl[bf], Bl + SWZ((uint32_t)((chB0 + bf * 16) * 128) + kof));
#pragma unroll
        for (int mf = 0; mf < NMF; mf++)
#pragma unroll
            for (int nf = 0; nf < 4; nf++)
                mma16816(&acc[mf][nf * 4], a[mf], bl[nf >> 1][nf & 1], bl[nf >> 1][(nf & 1) + 2]);
#pragma unroll
        for (int mf = 0; mf < NMF; mf++) ldsm_x4(a[mf], aHb[mf] + 32768 + SWZ((uint32_t)((pbA[mf] + kd) * 128) + kof));
#pragma unroll
        for (int mf = 0; mf < NMF; mf++)
#pragma unroll
            for (int nf = 0; nf < 4; nf++)
                mma16816(&acc[mf][nf * 4], a[mf], bh[nf >> 1][nf & 1], bh[nf >> 1][(nf & 1) + 2]);
    }
}

__device__ __forceinline__ void load_halo(char* sm, int slot, int img, int cb, int tid) {
#pragma unroll
    for (int t = 0; t < 8; t++) {
        int idx = tid + t * 512;
        int half = idx >> 11;
        int j = idx & 2047;
        int p = j >> 3, u = j & 7;
        const __nv_bfloat16* srcp = (half ? g_iml : g_imh) + ((size_t)img * 256 + p) * 1024 + cb * 64;
        uint4 v = ((const uint4*)srcp)[u];
        *(uint4*)(sm + slot * 65536 + half * 32768 + SWZ(p * 128 + u * 16)) = v;
    }
}

__global__ void __launch_bounds__(512) k_conv_mma(const float* __restrict__ conv_b) {
    extern __shared__ char sm_raw[];
    __shared__ float s_bias[128];
    const int tid = threadIdx.x;
    const int wid = tid >> 5, lane = tid & 31;
    const int wm = wid >> 2, wn = wid & 3;

    const int u0 = (blockIdx.x * NUNITS) / NCTA;
    const int u1 = ((blockIdx.x + 1) * NUNITS) / NCTA;
    const int cnt = u1 - u0;                 // 11 or 12
    const int n0 = u0 / 13;
    const int n1 = (u1 - 1) / 13;
    const int two = (n1 != n0);
    const int nmf = (cnt - wm + 3) >> 2;     // units: u0 + wm + 4*mf

    uint32_t raw = smem_u32(sm_raw);
    uint32_t base = (raw + 1023u) & ~1023u;
    char* sm = sm_raw + (base - raw);
    const uint32_t Bb = base + 131072;

    if (tid < 128) s_bias[tid] = conv_b[tid];

    float acc[3][16];
#pragma unroll
    for (int i = 0; i < 3; i++)
#pragma unroll
        for (int j = 0; j < 16; j++) acc[i][j] = 0.0f;

    int pbA[3], uN[3], uL[3];
    uint32_t aHb[3];
#pragma unroll
    for (int mf = 0; mf < 3; mf++) {
        int uu = u0 + wm + 4 * mf;
        if (uu >= u1) uu = u1 - 1;           // clamp (unused slots only)
        int nn = uu / 13, lu = uu - nn * 13;
        uN[mf] = nn; uL[mf] = lu;
        int o = lu * 16 + (lane & 15);
        if (o > 195) o = 195;
        int row = o / 14, col = o - row * 14;
        pbA[mf] = row * 16 + col;
        aHb[mf] = base + (uint32_t)((nn != n0) ? 65536 : 0);
    }
    const int kHi = (lane >> 4) * 16;
    const int chB0 = wn * 32 + (lane & 15);

    prefetch_B2(0, Bb, tid); cp_commit();

    for (int gs = 0; gs < 144; gs++) {
        int cb = gs / 9, kykx = gs - cb * 9;
        if (kykx == 0) {
            __syncthreads();                 // old halo reads done
            load_halo(sm, 0, n0, cb, tid);
            if (two) load_halo(sm, 1, n1, cb, tid);
        }
        if (gs + 1 < 144) {
            prefetch_B2(gs + 1, Bb, tid);    // writes buffer (gs+1)&1: freed by end-of-prev-iter sync
            cp_commit();
            asm volatile("cp.async.wait_group 1;" ::: "memory");
        } else {
            asm volatile("cp.async.wait_group 0;" ::: "memory");
        }
        __syncthreads();                     // publish B(gs) + halo

        int ky = kykx / 3, kx = kykx - ky * 3;
        int kd = ky * 16 + kx;
        uint32_t Bst = Bb + (uint32_t)(gs & 1) * 32768;

        if (nmf == 3) conv_stage<3>(aHb, Bst, kd, pbA, chB0, kHi, acc);
        else          conv_stage<2>(aHb, Bst, kd, pbA, chB0, kHi, acc);
        __syncthreads();                     // B(gs) reads done before overwrite
    }

    int g = lane >> 2, t2 = (lane & 3) * 2;
#pragma unroll
    for (int mf = 0; mf < 3; mf++) {
        if (mf < nmf) {
            int nn = uN[mf], lu = uL[mf];
            float* dst = g_xt + (size_t)nn * OO * CF;
#pragma unroll
            for (int nf = 0; nf < 4; nf++) {
                int ch = wn * 32 + nf * 8 + t2;
                float b0 = s_bias[ch], b1 = s_bias[ch + 1];
#pragma unroll
                for (int h = 0; h < 2; h++) {
                    int o = lu * 16 + g + h * 8;
                    if (o < OO) {
                        float v0 = acc[mf][nf * 4 + h * 2 + 0] + b0;
                        float v1 = acc[mf][nf * 4 + h * 2 + 1] + b1;
                        size_t r = (size_t)nn * OO + o;
                        dst[(size_t)o * CF + ch]     = v0;
                        dst[(size_t)o * CF + ch + 1] = v1;
                        __nv_bfloat16 h0, l0, h1, l1;
                        bf16split(v0, h0, l0);
                        bf16split(v1, h1, l1);
                        *(__nv_bfloat162*)(g_xth + r * CF + ch) = __nv_bfloat162{h0, h1};
                        *(__nv_bfloat162*)(g_xtl + r * CF + ch) = __nv_bfloat162{l0, l1};
                    }
                }
            }
        }
    }
}

// ---------------- generic GEMM stage (M=128, 16 warps as 2M x 8N) ----------------
__device__ __forceinline__ void gemm_stage(float (*acc)[16], uint32_t AhT, uint32_t AlT,
                                           uint32_t Bt, bool doLo,
                                           const uint32_t* rbase, uint32_t chbase, uint32_t kHi) {
#pragma unroll
    for (int ks = 0; ks < 4; ks++) {
        uint32_t b[2][4];
        ldsm_x4(b[0], Bt + SWZ(chbase + ks * 32 + kHi));
        ldsm_x4(b[1], Bt + SWZ(chbase + 16 * 128 + ks * 32 + kHi));
#pragma unroll
        for (int mf = 0; mf < 4; mf++) {
            uint32_t a[4];
            ldsm_x4(a, AhT + SWZ(rbase[mf] + ks * 32 + kHi));
#pragma unroll
            for (int nf = 0; nf < 4; nf++)
                mma16816(&acc[mf][nf * 4], a,
                         (nf & 1) ? b[nf >> 1][1] : b[nf >> 1][0],
                         (nf & 1) ? b[nf >> 1][3] : b[nf >> 1][2]);
            if (doLo) {
                uint32_t al[4];
                ldsm_x4(al, AlT + SWZ(rbase[mf] + ks * 32 + kHi));
#pragma unroll
                for (int nf = 0; nf < 4; nf++)
                    mma16816(&acc[mf][nf * 4], al,
                             (nf & 1) ? b[nf >> 1][1] : b[nf >> 1][0],
                             (nf & 1) ? b[nf >> 1][3] : b[nf >> 1][2]);
            }
        }
    }
}

__device__ __forceinline__ void load_A_tile(uint32_t smb, int r0, int tid) {
#pragma unroll
    for (int t = 0; t < 8; t++) {
        int idx = tid + t * 512;
        int half = idx >> 11;
        int j = idx & 2047;
        int row = j >> 4, cc = j & 15;
        int kblk = cc >> 3, u = cc & 7;
        const __nv_bfloat16* src = (half ? g_xtl : g_xth) + (size_t)(r0 + row) * 128 + kblk * 64 + u * 8;
        cp16(smb + half * 32768 + kblk * 16384 + SWZ(row * 128 + u * 16), src);
    }
}

// ---------------- h_psi as GEMM (196 M-tiles) ----------------
__global__ void __launch_bounds__(512) k_hpsi_mma(const float* __restrict__ hp_w1,
                                                  const float* __restrict__ hp_b1) {
    extern __shared__ char sm_raw[];
    __shared__ float s_w1[256];
    __shared__ float attp[8][128];

    const int tid = threadIdx.x;
    const int r0 = blockIdx.x * 128;
    const int wid = tid >> 5, lane = tid & 31;
    const int wm = wid & 1, wn = wid >> 1;

    uint32_t raw = smem_u32(sm_raw);
    uint32_t smb = (raw + 1023u) & ~1023u;
    const uint32_t Bbuf = smb + 65536;

    if (tid < 256) s_w1[tid] = hp_w1[tid];

    uint32_t rbase[4];
#pragma unroll
    for (int mf = 0; mf < 4; mf++) rbase[mf] = (uint32_t)(wm * 64 + mf * 16 + (lane & 15)) * 128;
    const uint32_t kHi = (lane >> 4) * 16;
    const uint32_t chbase = (uint32_t)((wn & 3) * 32 + (lane & 15)) * 128;
    const uint32_t Bwn = (wn >> 2) * 16384;

    float acc[4][16];
#pragma unroll
    for (int i = 0; i < 4; i++)
#pragma unroll
        for (int j = 0; j < 16; j++) acc[i][j] = 0.0f;

    {
        const uint8_t* src = g_hpBh;
#pragma unroll
        for (int t = 0; t < 4; t++) cp16(Bbuf + (tid + t * 512) * 16, src + (tid + t * 512) * 16);
        load_A_tile(smb, r0, tid);
        cp_commit();
    }

    for (int s = 0; s < 4; s++) {
        if (s < 3) {
            int sn = s + 1;
            const uint8_t* src = ((sn & 1) ? g_hpBl : g_hpBh) + (size_t)(sn >> 1) * 32768;
            uint32_t dstb = Bbuf + (sn & 1) * 32768;
#pragma unroll
            for (int t = 0; t < 4; t++) cp16(dstb + (tid + t * 512) * 16, src + (tid + t * 512) * 16);
            cp_commit();
            asm volatile("cp.async.wait_group 1;" ::: "memory");
        } else {
            asm volatile("cp.async.wait_group 0;" ::: "memory");
        }
        __syncthreads();
        int kblk = s >> 1;
        gemm_stage(acc, smb + kblk * 16384, smb + 32768 + kblk * 16384,
                   Bbuf + (s & 1) * 32768 + Bwn, (s & 1) == 0, rbase, chbase, kHi);
        __syncthreads();
    }

    int g = lane >> 2, t2 = (lane & 3) * 2;
    float psum[4][2];
#pragma unroll
    for (int mf = 0; mf < 4; mf++) { psum[mf][0] = 0.0f; psum[mf][1] = 0.0f; }
#pragma unroll
    for (int mf = 0; mf < 4; mf++)
#pragma unroll
        for (int h = 0; h < 2; h++) {
            int row = wm * 64 + mf * 16 + g + h * 8;
            int r = r0 + row;
            int n = r / OO, o = r - n * OO;
#pragma unroll
            for (int nf = 0; nf < 4; nf++)
#pragma unroll
                for (int j = 0; j < 2; j++) {
                    int ch = wn * 32 + nf * 8 + t2 + j;
                    float v = acc[mf][nf * 4 + h * 2 + j] + g_pero_hp[o * 256 + ch] + g_pern_hp[n * 256 + ch];
                    psum[mf][h] += fmaxf(v, 0.0f) * s_w1[ch];
                }
        }
#pragma unroll
    for (int mf = 0; mf < 4; mf++)
#pragma unroll
        for (int h = 0; h < 2; h++) {
            float p = psum[mf][h];
            p += __shfl_xor_sync(0xffffffffu, p, 1);
            p += __shfl_xor_sync(0xffffffffu, p, 2);
            if ((lane & 3) == 0) attp[wn][wm * 64 + mf * 16 + g + h * 8] = p;
        }
    __syncthreads();
    if (tid < 128) {
        float a = hp_b1[0];
#pragma unroll
        for (int w = 0; w < 8; w++) a += attp[w][tid];
        g_att[r0 + tid] = a;
    }
}

// ---------------- fused g_theta (layer1 + layer2 + object-sum) ----------------
__global__ void __launch_bounds__(512) k_gt_mma(const float* __restrict__ gt_b1) {
    extern __shared__ char sm_raw[];
    __shared__ float s_b1[256];
    __shared__ float relp[2][256];

    const int tid = threadIdx.x;
    const int r0 = blockIdx.x * 128;
    const int wid = tid >> 5, lane = tid & 31;
    const int wm = wid & 1, wn = wid >> 1;

    uint32_t raw = smem_u32(sm_raw);
    uint32_t smb = (raw + 1023u) & ~1023u;
    const uint32_t Bbuf = smb + 131072;

    if (tid < 256) s_b1[tid] = gt_b1[tid];
    if (tid < 512) ((float*)relp)[tid] = 0.0f;

    uint32_t rbase[4];
#pragma unroll
    for (int mf = 0; mf < 4; mf++) rbase[mf] = (uint32_t)(wm * 64 + mf * 16 + (lane & 15)) * 128;
    const uint32_t kHi = (lane >> 4) * 16;
    const uint32_t chbase = (uint32_t)((wn & 3) * 32 + (lane & 15)) * 128;
    const uint32_t Bwn = (wn >> 2) * 16384;
    const int g = lane >> 2, t2 = (lane & 3) * 2;

    float acc[4][16];
#pragma unroll
    for (int i = 0; i < 4; i++)
#pragma unroll
        for (int j = 0; j < 16; j++) acc[i][j] = 0.0f;

    {
#pragma unroll
        for (int t = 0; t < 4; t++) cp16(Bbuf + (tid + t * 512) * 16, g_gt0Bh + (tid + t * 512) * 16);
        load_A_tile(smb, r0, tid);
        cp_commit();
    }

    for (int s = 0; s < 12; s++) {
        if (s < 11) {
            int sn = s + 1;
            const uint8_t* basep;
            int kblk;
            if (sn < 4) { basep = (sn & 1) ? g_gt0Bl : g_gt0Bh; kblk = sn >> 1; }
            else        { int t = sn - 4; basep = (t & 1) ? g_gt1Bl : g_gt1Bh; kblk = t >> 1; }
            const uint8_t* src = basep + (size_t)kblk * 32768;
            uint32_t dstb = Bbuf + (sn & 1) * 32768;
#pragma unroll
            for (int t = 0; t < 4; t++) cp16(dstb + (tid + t * 512) * 16, src + (tid + t * 512) * 16);
            cp_commit();
            asm volatile("cp.async.wait_group 1;" ::: "memory");
        } else {
            asm volatile("cp.async.wait_group 0;" ::: "memory");
        }
        __syncthreads();

        if (s < 4) {
            int kblk = s >> 1;
            gemm_stage(acc, smb + kblk * 16384, smb + 32768 + kblk * 16384,
                       Bbuf + (s & 1) * 32768 + Bwn, (s & 1) == 0, rbase, chbase, kHi);
        } else {
            int kt = (s - 4) >> 1;
            gemm_stage(acc, smb + kt * 16384, smb + 65536 + kt * 16384,
                       Bbuf + (s & 1) * 32768 + Bwn, (s & 1) == 0, rbase, chbase, kHi);
        }
        __syncthreads();

        if (s == 3) {
#pragma unroll
            for (int mf = 0; mf < 4; mf++)
#pragma unroll
                for (int h = 0; h < 2; h++) {
                    int row = wm * 64 + mf * 16 + g + h * 8;
                    int r = r0 + row;
                    int n = r / OO, o = r - n * OO;
#pragma unroll
                    for (int nf = 0; nf < 4; nf++) {
                        int ch0 = wn * 32 + nf * 8 + t2;
                        float v0 = acc[mf][nf * 4 + h * 2 + 0] + g_pero_gt[o * 256 + ch0]     + g_pern_gt[n * 256 + ch0];
                        float v1 = acc[mf][nf * 4 + h * 2 + 1] + g_pero_gt[o * 256 + ch0 + 1] + g_pern_gt[n * 256 + ch0 + 1];
                        v0 = fmaxf(v0, 0.0f); v1 = fmaxf(v1, 0.0f);
                        __nv_bfloat16 h0, l0, h1, l1;
                        bf16split(v0, h0, l0);
                        bf16split(v1, h1, l1);
                        uint32_t off = (uint32_t)(ch0 >> 6) * 16384 + SWZ(row * 128 + (ch0 & 63) * 2);
                        *(__nv_bfloat162*)(sm_raw + (smb - raw) + off)         = __nv_bfloat162{h0, h1};
                        *(__nv_bfloat162*)(sm_raw + (smb - raw) + 65536 + off) = __nv_bfloat162{l0, l1};
                    }
                }
#pragma unroll
            for (int i = 0; i < 4; i++)
#pragma unroll
                for (int j = 0; j < 16; j++) acc[i][j] = 0.0f;
            __syncthreads();
        }
    }

    const int n0 = r0 / OO;
    const int n1 = (r0 + 127) / OO;
#pragma unroll
    for (int mf = 0; mf < 4; mf++)
#pragma unroll
        for (int h = 0; h < 2; h++) {
            int row = wm * 64 + mf * 16 + g + h * 8;
            int r = r0 + row;
            int n = r / OO;
            int nn = (n != n0);
#pragma unroll
            for (int nf = 0; nf < 4; nf++)
#pragma unroll
                for (int j = 0; j < 2; j++) {
                    int ch = wn * 32 + nf * 8 + t2 + j;
                    float v = fmaxf(acc[mf][nf * 4 + h * 2 + j] + s_b1[ch], 0.0f);
                    atomicAdd(&relp[nn][ch], v);
                }
        }
    __syncthreads();
    if (tid < 256) {
        atomicAdd(&g_rel[n0 * 256 + tid], relp[0][tid]);
    } else {
        int ch = tid - 256;
        if (n1 != n0) atomicAdd(&g_rel[n1 * 256 + ch], relp[1][ch]);
    }
}

// ---------------- softmax + soft selection + pern_gt finish (512 threads) ----------------
__global__ void __launch_bounds__(512) k_softsel(const float* __restrict__ gt_w0) {
    int n = blockIdx.x;
    int tid = threadIdx.x;
    __shared__ float att_s[OO];
    __shared__ float red_s[16];
    __shared__ float selp[4][128];
    __shared__ float sel_s[CED];
    __shared__ float pgp[2][256];

    if (tid < OO) att_s[tid] = g_att[n * OO + tid];
    __syncthreads();

    float v = (tid < OO) ? att_s[tid] : -1e30f;
#pragma unroll
    for (int off = 16; off > 0; off >>= 1) v = fmaxf(v, __shfl_xor_sync(0xffffffffu, v, off));
    if ((tid & 31) == 0) red_s[tid >> 5] = v;
    __syncthreads();
    float m = -1e30f;
#pragma unroll
    for (int i = 0; i < 16; i++) m = fmaxf(m, red_s[i]);
    __syncthreads();

    float e = (tid < OO) ? expf(att_s[tid] - m) : 0.0f;
    float sv = e;
#pragma unroll
    for (int off = 16; off > 0; off >>= 1) sv += __shfl_xor_sync(0xffffffffu, sv, off);
    if ((tid & 31) == 0) red_s[tid >> 5] = sv;
    __syncthreads();
    float tot = 0.0f;
#pragma unroll
    for (int i = 0; i < 16; i++) tot += red_s[i];
    if (tid < OO) att_s[tid] = e / tot;
    __syncthreads();

    {
        const float* xtn = g_xt + (size_t)n * OO * CF;
        int q = tid >> 7, d = tid & 127;
        int o0 = q * 49;
        float a[8];
#pragma unroll
        for (int k = 0; k < 8; k++) a[k] = 0.0f;
#pragma unroll
        for (int i = 0; i < 48; i += 8) {
#pragma unroll
            for (int k = 0; k < 8; k++)
                a[k] = fmaf(att_s[o0 + i + k], xtn[(size_t)(o0 + i + k) * CF + d], a[k]);
        }
        a[0] = fmaf(att_s[o0 + 48], xtn[(size_t)(o0 + 48) * CF + d], a[0]);
        selp[q][d] = ((a[0] + a[1]) + (a[2] + a[3])) + ((a[4] + a[5]) + (a[6] + a[7]));
    }
    __syncthreads();
    if (tid < 128) {
        float s = (selp[0][tid] + selp[1][tid]) + (selp[2][tid] + selp[3][tid]);
        g_sel[n * CED + tid] = s;
        sel_s[tid] = s;
    } else if (tid == 128) {
        float a = 0.0f;
        for (int o = 0; o < OO; o++) a = fmaf(att_s[o], xcoord(o), a);
        g_sel[n * CED + 128] = a;
        sel_s[128] = a;
    } else if (tid == 129) {
        float a = 0.0f;
        for (int o = 0; o < OO; o++) a = fmaf(att_s[o], ycoord(o), a);
        g_sel[n * CED + 129] = a;
        sel_s[129] = a;
    }
    __syncthreads();

    {
        int p = tid >> 8, ch = tid & 255;
        int d0 = p * 65, d1 = d0 + 65;
        float s = 0.0f;
#pragma unroll 4
        for (int d = d0; d < d1; d++)
            s = fmaf(sel_s[d], gt_w0[(QD + d) * 256 + ch], s);
        pgp[p][ch] = s;
    }
    __syncthreads();
    if (tid < 256)
        g_pern_gt[n * 256 + tid] += pgp[0][tid] + pgp[1][tid];
}

// ---------------- f_phi head ----------------
__global__ void __launch_bounds__(256) k_fphi(const float* __restrict__ fp_w0,
                                              const float* __restrict__ fp_b0,
                                              const float* __restrict__ fp_w1,
                                              const float* __restrict__ fp_b1,
                                              float* __restrict__ out) {
    int n = blockIdx.x;
    int tid = threadIdx.x;
    __shared__ float f_s[FP];

    const float* rel = g_rel + n * GT;
    float s = fp_b0[tid];
#pragma unroll 4
    for (int h = 0; h < GT; h++)
        s = fmaf(rel[h], fp_w0[h * FP + tid], s);
    f_s[tid] = fmaxf(s, 0.0f);
    __syncthreads();

    if (tid < ASZ) {
        float s2 = fp_b1[tid];
#pragma unroll 4
        for (int h = 0; h < FP; h++)
            s2 = fmaf(f_s[h], fp_w1[h * ASZ + tid], s2);
        out[n * ASZ + tid] = s2;
    }
}

// ---------------- launch ----------------
extern "C" void kernel_launch(void* const* d_in, const int* in_sizes, int n_in,
                              void* d_out, int out_size) {
    const float* image  = (const float*)d_in[0];
    const float* code   = (const float*)d_in[1];
    const float* conv_w = (const float*)d_in[2];
    const float* conv_b = (const float*)d_in[3];
    const float* hp_w0  = (const float*)d_in[4];
    const float* hp_b0  = (const float*)d_in[5];
    const float* hp_w1  = (const float*)d_in[6];
    const float* hp_b1  = (const float*)d_in[7];
    const float* gt_w0  = (const float*)d_in[8];
    const float* gt_b0  = (const float*)d_in[9];
    const float* gt_w1  = (const float*)d_in[10];
    const float* gt_b1  = (const float*)d_in[11];
    const float* fp_w0  = (const float*)d_in[12];
    const float* fp_b0  = (const float*)d_in[13];
    const float* fp_w1  = (const float*)d_in[14];
    const float* fp_b1  = (const float*)d_in[15];
    float* out = (float*)d_out;

    cudaFuncSetAttribute(k_conv_mma, cudaFuncAttributeMaxDynamicSharedMemorySize, CONV_SMEM);
    cudaFuncSetAttribute(k_hpsi_mma, cudaFuncAttributeMaxDynamicSharedMemorySize, 132096);
    cudaFuncSetAttribute(k_gt_mma,   cudaFuncAttributeMaxDynamicSharedMemorySize, 197632);

    k_prep_all<<<PREP_BLOCKS, 256>>>(image, conv_w, code, hp_w0, hp_b0, gt_w0, gt_b0, gt_w1);
    k_conv_mma<<<NCTA, 512, CONV_SMEM>>>(conv_b);
    k_hpsi_mma<<<196, 512, 132096>>>(hp_w1, hp_b1);
    k_softsel<<<NB, 512>>>(gt_w0);
    k_gt_mma<<<196, 512, 197632>>>(gt_b1);
    k_fphi<<<NB, 256>>>(fp_w0, fp_b0, fp_w1, fp_b1, out);
}

// round 15
// speedup vs baseline: 1.2529x; 1.0529x over previous
#include <cuda_runtime.h>
#include <cuda_bf16.h>
#include <cstdint>

// ---------------- problem constants ----------------
#define NB    128
#define CIN   1024
#define HH    14
#define WW    14
#define OO    196
#define CF    128
#define TH    128
#define QD    258
#define CED   130
#define PD    388
#define HP    256
#define GT    256
#define FP    256
#define ASZ   32
#define NROWS (NB * OO)     // 25088

// ---------------- scratch ----------------
// NOTE: g_imh/g_iml halo borders rely on CUDA zero-initialization of __device__
// globals; k_prep_all writes interior cells only, nothing ever writes borders.
__device__ __align__(16) __nv_bfloat16 g_imh[NB * 256 * CIN];
__device__ __align__(16) __nv_bfloat16 g_iml[NB * 256 * CIN];
__device__ __align__(16) uint8_t g_wbh[144 * 16384];
__device__ __align__(16) uint8_t g_wbl[144 * 16384];
__device__ __align__(16) float g_xt[NB * OO * CF];
__device__ __align__(16) __nv_bfloat16 g_xth[NB * OO * CF];
__device__ __align__(16) __nv_bfloat16 g_xtl[NB * OO * CF];
__device__ __align__(16) uint8_t g_hpBh[4 * 16384],  g_hpBl[4 * 16384];
__device__ __align__(16) uint8_t g_gt0Bh[4 * 16384], g_gt0Bl[4 * 16384];
__device__ __align__(16) uint8_t g_gt1Bh[8 * 16384], g_gt1Bl[8 * 16384];
__device__ float g_pero_hp[OO * 256], g_pern_hp[NB * 256];
__device__ float g_pero_gt[OO * 256], g_pern_gt[NB * 256];
__device__ float g_att[NB * OO];
__device__ float g_sel[NB * CED];
__device__ float g_rel[NB * GT];

__device__ __forceinline__ float xcoord(int o) { return -1.0f + 2.0f * (float)(o / WW) / 13.0f; }
__device__ __forceinline__ float ycoord(int o) { return -1.0f + 2.0f * (float)(o % WW) / 13.0f; }

// ---------------- helpers ----------------
#define SWZ(x) ((x) ^ (((x) >> 3) & 0x70))

__device__ __forceinline__ uint32_t smem_u32(const void* p) {
    uint32_t a;
    asm("{ .reg .u64 t; cvta.to.shared.u64 t, %1; cvt.u32.u64 %0, t; }" : "=r"(a) : "l"(p));
    return a;
}
__device__ __forceinline__ void ldsm_x4(uint32_t* r, uint32_t addr) {
    asm volatile("ldmatrix.sync.aligned.m8n8.x4.shared.b16 {%0,%1,%2,%3}, [%4];"
                 : "=r"(r[0]), "=r"(r[1]), "=r"(r[2]), "=r"(r[3]) : "r"(addr));
}
__device__ __forceinline__ void mma16816(float* c, const uint32_t* a, uint32_t b0, uint32_t b1) {
    asm volatile("mma.sync.aligned.m16n8k16.row.col.f32.bf16.bf16.f32 "
                 "{%0,%1,%2,%3}, {%4,%5,%6,%7}, {%8,%9}, {%0,%1,%2,%3};"
                 : "+f"(c[0]), "+f"(c[1]), "+f"(c[2]), "+f"(c[3])
                 : "r"(a[0]), "r"(a[1]), "r"(a[2]), "r"(a[3]), "r"(b0), "r"(b1));
}
__device__ __forceinline__ void cp16(uint32_t dst, const void* src) {
    asm volatile("cp.async.cg.shared.global [%0], [%1], 16;" :: "r"(dst), "l"(src));
}
__device__ __forceinline__ void cp_commit() { asm volatile("cp.async.commit_group;" ::: "memory"); }
__device__ __forceinline__ void bf16split(float v, __nv_bfloat16& h, __nv_bfloat16& l) {
    h = __float2bfloat16(v);
    l = __float2bfloat16(v - __bfloat162float(h));
}

// ---------------- mega prep kernel ----------------
#define PREP_BLOCKS 19780

__device__ __forceinline__ void mlppack_one(const float* __restrict__ src,
                                            uint8_t* __restrict__ dstH,
                                            uint8_t* __restrict__ dstL, int idx) {
    int k6    = idx & 63;
    int ch    = (idx >> 6) & 127;
    int chblk = (idx >> 13) & 1;
    int kblk  = idx >> 14;
    float v = src[(kblk * 64 + k6) * 256 + chblk * 128 + ch];
    __nv_bfloat16 hi, lo; bf16split(v, hi, lo);
    int off = (kblk * 2 + chblk) * 16384 + SWZ(ch * 128 + k6 * 2);
    *(__nv_bfloat16*)(dstH + off) = hi;
    *(__nv_bfloat16*)(dstL + off) = lo;
}

__global__ void __launch_bounds__(256) k_prep_all(
    const float* __restrict__ image, const float* __restrict__ conv_w,
    const float* __restrict__ code,
    const float* __restrict__ hp_w0, const float* __restrict__ hp_b0,
    const float* __restrict__ gt_w0, const float* __restrict__ gt_b0,
    const float* __restrict__ gt_w1)
{
    int b = blockIdx.x, tid = threadIdx.x;

    if (b < 4608) {
        int idx = b * 256 + tid;
        int j    = idx & 63;
        int ch   = (idx >> 6) & 127;
        int cb   = (idx >> 13) & 15;
        int kykx = idx >> 17;
        int cin  = cb * 64 + j;
        float v = conv_w[ch * (CIN * 9) + cin * 9 + kykx];
        __nv_bfloat16 hi, lo; bf16split(v, hi, lo);
        int dst = (kykx * 16 + cb) * 16384 + SWZ(ch * 128 + j * 2);
        *(__nv_bfloat16*)(g_wbh + dst) = hi;
        *(__nv_bfloat16*)(g_wbl + dst) = lo;
    } else if (b < 4736) {
        mlppack_one(hp_w0, g_hpBh, g_hpBl, (b - 4608) * 256 + tid);
    } else if (b < 4864) {
        mlppack_one(gt_w0, g_gt0Bh, g_gt0Bl, (b - 4736) * 256 + tid);
    } else if (b < 5120) {
        mlppack_one(gt_w1, g_gt1Bh, g_gt1Bl, (b - 4864) * 256 + tid);
    } else if (b < 19456) {
        int bb = b - 5120;
        int pb = bb % 7, cbk = (bb / 7) % 16, n = bb / 112;
        __shared__ float t[64][33];
        int pos0 = pb * 32;
        for (int e = tid; e < 64 * 32; e += 256) {
            int ci = e >> 5, p = e & 31;
            int pos = pos0 + p;
            float v = 0.0f;
            if (pos < OO) v = image[((size_t)n * CIN + cbk * 64 + ci) * OO + pos];
            t[ci][p] = v;
        }
        __syncthreads();
        for (int e = tid; e < 64 * 32; e += 256) {
            int p = e >> 6, ci = e & 63;
            int pos = pos0 + p;
            if (pos < OO) {
                int row = pos / 14, col = pos - row * 14;
                int hp  = (row + 1) * 16 + (col + 1);
                size_t off = ((size_t)n * 256 + hp) * 1024 + cbk * 64 + ci;
                __nv_bfloat16 hi, lo; bf16split(t[ci][p], hi, lo);
                g_imh[off] = hi;
                g_iml[off] = lo;
            }
        }
    } else if (b < 19652) {
        int o = b - 19456, ch = tid;
        float xc = xcoord(o), yc = ycoord(o);
        g_pero_hp[o * 256 + ch] = xc * hp_w0[128 * 256 + ch] + yc * hp_w0[129 * 256 + ch];
        g_pero_gt[o * 256 + ch] = xc * gt_w0[128 * 256 + ch] + yc * gt_w0[129 * 256 + ch];
    } else {
        int n = b - 19652, ch = tid;
        float sh = hp_b0[ch], sg = gt_b0[ch];
#pragma unroll 4
        for (int d = 0; d < 128; d++) {
            float c = code[n * 128 + d];
            sh = fmaf(c, hp_w0[(130 + d) * 256 + ch], sh);
            sg = fmaf(c, gt_w0[(130 + d) * 256 + ch], sg);
        }
        g_pern_hp[n * 256 + ch] = sh;
        g_pern_gt[n * 256 + ch] = sg;
        g_rel[n * 256 + ch] = 0.0f;
    }
}

// ---------------- conv: global unit-split, 148 CTAs, one wave (round-14, passing) ----------------
#define NUNITS 1664
#define NCTA   148
#define CONV_SMEM 197632

__device__ __forceinline__ void prefetch_B2(int g, uint32_t Bb, int tid) {
    int cb = g / 9, kykx = g - cb * 9;
    size_t off = (size_t)(kykx * 16 + cb) * 16384;
    uint32_t dst = Bb + (uint32_t)(g & 1) * 32768;
#pragma unroll
    for (int t = 0; t < 2; t++) {
        int i = tid + t * 512;
        cp16(dst + i * 16,         g_wbh + off + i * 16);
        cp16(dst + 16384 + i * 16, g_wbl + off + i * 16);
    }
}

template<int NMF>
__device__ __forceinline__ void conv_stage(const uint32_t* aHb, uint32_t Bstage,
                                           int kd, const int* pbA, int chB0, int kHi,
                                           float (*acc)[16]) {
    uint32_t Bh = Bstage, Bl = Bstage + 16384;
#pragma unroll
    for (int ks = 0; ks < 4; ks++) {
        uint32_t bh[2][4], bl[2][4], a[NMF][4];
        uint32_t kof = (uint32_t)(ks * 32 + kHi);
#pragma unroll
        for (int bf = 0; bf < 2; bf++) ldsm_x4(bh[bf], Bh + SWZ((uint32_t)((chB0 + bf * 16) * 128) + kof));
#pragma unroll
        for (int mf = 0; mf < NMF; mf++) ldsm_x4(a[mf], aHb[mf] + SWZ((uint32_t)((pbA[mf] + kd) * 128) + kof));
#pragma unroll
        for (int mf = 0; mf < NMF; mf++)
#pragma unroll
            for (int nf = 0; nf < 4; nf++)
                mma16816(&acc[mf][nf * 4], a[mf], bh[nf >> 1][nf & 1], bh[nf >> 1][(nf & 1) + 2]);
#pragma unroll
        for (int bf = 0; bf < 2; bf++) ldsm_x4(bl[bf], Bl + SWZ((uint32_t)((chB0 + bf * 16) * 128) + kof));
#pragma unroll
        for (int mf = 0; mf < NMF; mf++)
#pragma unroll
            for (int nf = 0; nf < 4; nf++)
                mma16816(&acc[mf][nf * 4], a[mf], bl[nf >> 1][nf & 1], bl[nf >> 1][(nf & 1) + 2]);
#pragma unroll
        for (int mf = 0; mf < NMF; mf++) ldsm_x4(a[mf], aHb[mf] + 32768 + SWZ((uint32_t)((pbA[mf] + kd) * 128) + kof));
#pragma unroll
        for (int mf = 0; mf < NMF; mf++)
#pragma unroll
            for (int nf = 0; nf < 4; nf++)
                mma16816(&acc[mf][nf * 4], a[mf], bh[nf >> 1][nf & 1], bh[nf >> 1][(nf & 1) + 2]);
    }
}

__device__ __forceinline__ void load_halo(char* sm, int slot, int img, int cb, int tid) {
#pragma unroll
    for (int t = 0; t < 8; t++) {
        int idx = tid + t * 512;
        int half = idx >> 11;
        int j = idx & 2047;
        int p = j >> 3, u = j & 7;
        const __nv_bfloat16* srcp = (half ? g_iml : g_imh) + ((size_t)img * 256 + p) * 1024 + cb * 64;
        uint4 v = ((const uint4*)srcp)[u];
        *(uint4*)(sm + slot * 65536 + half * 32768 + SWZ(p * 128 + u * 16)) = v;
    }
}

__global__ void __launch_bounds__(512) k_conv_mma(const float* __restrict__ conv_b) {
    extern __shared__ char sm_raw[];
    __shared__ float s_bias[128];
    const int tid = threadIdx.x;
    const int wid = tid >> 5, lane = tid & 31;
    const int wm = wid >> 2, wn = wid & 3;

    const int u0 = (blockIdx.x * NUNITS) / NCTA;
    const int u1 = ((blockIdx.x + 1) * NUNITS) / NCTA;
    const int cnt = u1 - u0;
    const int n0 = u0 / 13;
    const int n1 = (u1 - 1) / 13;
    const int two = (n1 != n0);
    const int nmf = (cnt - wm + 3) >> 2;

    uint32_t raw = smem_u32(sm_raw);
    uint32_t base = (raw + 1023u) & ~1023u;
    char* sm = sm_raw + (base - raw);
    const uint32_t Bb = base + 131072;

    if (tid < 128) s_bias[tid] = conv_b[tid];

    float acc[3][16];
#pragma unroll
    for (int i = 0; i < 3; i++)
#pragma unroll
        for (int j = 0; j < 16; j++) acc[i][j] = 0.0f;

    int pbA[3], uN[3], uL[3];
    uint32_t aHb[3];
#pragma unroll
    for (int mf = 0; mf < 3; mf++) {
        int uu = u0 + wm + 4 * mf;
        if (uu >= u1) uu = u1 - 1;
        int nn = uu / 13, lu = uu - nn * 13;
        uN[mf] = nn; uL[mf] = lu;
        int o = lu * 16 + (lane & 15);
        if (o > 195) o = 195;
        int row = o / 14, col = o - row * 14;
        pbA[mf] = row * 16 + col;
        aHb[mf] = base + (uint32_t)((nn != n0) ? 65536 : 0);
    }
    const int kHi = (lane >> 4) * 16;
    const int chB0 = wn * 32 + (lane & 15);

    prefetch_B2(0, Bb, tid); cp_commit();

    for (int gs = 0; gs < 144; gs++) {
        int cb = gs / 9, kykx = gs - cb * 9;
        if (kykx == 0) {
            __syncthreads();
            load_halo(sm, 0, n0, cb, tid);
            if (two) load_halo(sm, 1, n1, cb, tid);
        }
        if (gs + 1 < 144) {
            prefetch_B2(gs + 1, Bb, tid);
            cp_commit();
            asm volatile("cp.async.wait_group 1;" ::: "memory");
        } else {
            asm volatile("cp.async.wait_group 0;" ::: "memory");
        }
        __syncthreads();

        int ky = kykx / 3, kx = kykx - ky * 3;
        int kd = ky * 16 + kx;
        uint32_t Bst = Bb + (uint32_t)(gs & 1) * 32768;

        if (nmf == 3) conv_stage<3>(aHb, Bst, kd, pbA, chB0, kHi, acc);
        else          conv_stage<2>(aHb, Bst, kd, pbA, chB0, kHi, acc);
        __syncthreads();
    }

    int g = lane >> 2, t2 = (lane & 3) * 2;
#pragma unroll
    for (int mf = 0; mf < 3; mf++) {
        if (mf < nmf) {
            int nn = uN[mf], lu = uL[mf];
            float* dst = g_xt + (size_t)nn * OO * CF;
#pragma unroll
            for (int nf = 0; nf < 4; nf++) {
                int ch = wn * 32 + nf * 8 + t2;
                float b0 = s_bias[ch], b1 = s_bias[ch + 1];
#pragma unroll
                for (int h = 0; h < 2; h++) {
                    int o = lu * 16 + g + h * 8;
                    if (o < OO) {
                        float v0 = acc[mf][nf * 4 + h * 2 + 0] + b0;
                        float v1 = acc[mf][nf * 4 + h * 2 + 1] + b1;
                        size_t r = (size_t)nn * OO + o;
                        dst[(size_t)o * CF + ch]     = v0;
                        dst[(size_t)o * CF + ch + 1] = v1;
                        __nv_bfloat16 h0, l0, h1, l1;
                        bf16split(v0, h0, l0);
                        bf16split(v1, h1, l1);
                        *(__nv_bfloat162*)(g_xth + r * CF + ch) = __nv_bfloat162{h0, h1};
                        *(__nv_bfloat162*)(g_xtl + r * CF + ch) = __nv_bfloat162{l0, l1};
                    }
                }
            }
        }
    }
}

// ---------------- M=96 GEMM machinery (262 tiles; 2M x 8N warps, mf<3) ----------------
#define GM    96
#define NT96  262            // ceil(25088/96)
#define A_ATOM 12288         // 96 rows x 64 cols bf16

__device__ __forceinline__ void gemm_stage96(float (*acc)[16], uint32_t AhT, uint32_t AlT,
                                             uint32_t Bt, bool doLo,
                                             const uint32_t* rbase, uint32_t chbase, uint32_t kHi) {
#pragma unroll
    for (int ks = 0; ks < 4; ks++) {
        uint32_t b[2][4];
        ldsm_x4(b[0], Bt + SWZ(chbase + ks * 32 + kHi));
        ldsm_x4(b[1], Bt + SWZ(chbase + 16 * 128 + ks * 32 + kHi));
#pragma unroll
        for (int mf = 0; mf < 3; mf++) {
            uint32_t a[4];
            ldsm_x4(a, AhT + SWZ(rbase[mf] + ks * 32 + kHi));
#pragma unroll
            for (int nf = 0; nf < 4; nf++)
                mma16816(&acc[mf][nf * 4], a,
                         (nf & 1) ? b[nf >> 1][1] : b[nf >> 1][0],
                         (nf & 1) ? b[nf >> 1][3] : b[nf >> 1][2]);
            if (doLo) {
                uint32_t al[4];
                ldsm_x4(al, AlT + SWZ(rbase[mf] + ks * 32 + kHi));
#pragma unroll
                for (int nf = 0; nf < 4; nf++)
                    mma16816(&acc[mf][nf * 4], al,
                             (nf & 1) ? b[nf >> 1][1] : b[nf >> 1][0],
                             (nf & 1) ? b[nf >> 1][3] : b[nf >> 1][2]);
            }
        }
    }
}

// A1 layout: [Ah k0 | Ah k1 | Al k0 | Al k1], each A_ATOM; rows clamped to NROWS-1.
__device__ __forceinline__ void load_A_tile96(uint32_t smb, int r0, int tid) {
#pragma unroll
    for (int t = 0; t < 6; t++) {
        int idx = tid + t * 512;              // 0..3071
        int half = idx >= 1536;
        int j = idx - half * 1536;
        int row = j >> 4, cc = j & 15;
        int kblk = cc >> 3, u = cc & 7;
        int rr = r0 + row; if (rr >= NROWS) rr = NROWS - 1;
        const __nv_bfloat16* src = (half ? g_xtl : g_xth) + (size_t)rr * 128 + kblk * 64 + u * 8;
        cp16(smb + half * 24576 + kblk * A_ATOM + SWZ(row * 128 + u * 16), src);
    }
}

// ---------------- h_psi as GEMM (262 M=96 tiles) ----------------
__global__ void __launch_bounds__(512) k_hpsi_mma(const float* __restrict__ hp_w1,
                                                  const float* __restrict__ hp_b1) {
    extern __shared__ char sm_raw[];
    __shared__ float s_w1[256];
    __shared__ float attp[8][GM];

    const int tid = threadIdx.x;
    const int r0 = blockIdx.x * GM;
    const int wid = tid >> 5, lane = tid & 31;
    const int wm = wid & 1, wn = wid >> 1;

    uint32_t raw = smem_u32(sm_raw);
    uint32_t smb = (raw + 1023u) & ~1023u;
    const uint32_t Bbuf = smb + 49152;

    if (tid < 256) s_w1[tid] = hp_w1[tid];

    uint32_t rbase[3];
#pragma unroll
    for (int mf = 0; mf < 3; mf++) rbase[mf] = (uint32_t)(wm * 48 + mf * 16 + (lane & 15)) * 128;
    const uint32_t kHi = (lane >> 4) * 16;
    const uint32_t chbase = (uint32_t)((wn & 3) * 32 + (lane & 15)) * 128;
    const uint32_t Bwn = (wn >> 2) * 16384;

    float acc[3][16];
#pragma unroll
    for (int i = 0; i < 3; i++)
#pragma unroll
        for (int j = 0; j < 16; j++) acc[i][j] = 0.0f;

    {
        const uint8_t* src = g_hpBh;
#pragma unroll
        for (int t = 0; t < 4; t++) cp16(Bbuf + (tid + t * 512) * 16, src + (tid + t * 512) * 16);
        load_A_tile96(smb, r0, tid);
        cp_commit();
    }

    for (int s = 0; s < 4; s++) {
        if (s < 3) {
            int sn = s + 1;
            const uint8_t* src = ((sn & 1) ? g_hpBl : g_hpBh) + (size_t)(sn >> 1) * 32768;
            uint32_t dstb = Bbuf + (sn & 1) * 32768;
#pragma unroll
            for (int t = 0; t < 4; t++) cp16(dstb + (tid + t * 512) * 16, src + (tid + t * 512) * 16);
            cp_commit();
            asm volatile("cp.async.wait_group 1;" ::: "memory");
        } else {
            asm volatile("cp.async.wait_group 0;" ::: "memory");
        }
        __syncthreads();
        int kblk = s >> 1;
        gemm_stage96(acc, smb + kblk * A_ATOM, smb + 24576 + kblk * A_ATOM,
                     Bbuf + (s & 1) * 32768 + Bwn, (s & 1) == 0, rbase, chbase, kHi);
        __syncthreads();
    }

    int g = lane >> 2, t2 = (lane & 3) * 2;
    float psum[3][2];
#pragma unroll
    for (int mf = 0; mf < 3; mf++) { psum[mf][0] = 0.0f; psum[mf][1] = 0.0f; }
#pragma unroll
    for (int mf = 0; mf < 3; mf++)
#pragma unroll
        for (int h = 0; h < 2; h++) {
            int row = wm * 48 + mf * 16 + g + h * 8;
            int r = r0 + row; if (r >= NROWS) r = NROWS - 1;   // clamp (garbage rows masked at write)
            int n = r / OO, o = r - n * OO;
#pragma unroll
            for (int nf = 0; nf < 4; nf++)
#pragma unroll
                for (int j = 0; j < 2; j++) {
                    int ch = wn * 32 + nf * 8 + t2 + j;
                    float v = acc[mf][nf * 4 + h * 2 + j] + g_pero_hp[o * 256 + ch] + g_pern_hp[n * 256 + ch];
                    psum[mf][h] += fmaxf(v, 0.0f) * s_w1[ch];
                }
        }
#pragma unroll
    for (int mf = 0; mf < 3; mf++)
#pragma unroll
        for (int h = 0; h < 2; h++) {
            float p = psum[mf][h];
            p += __shfl_xor_sync(0xffffffffu, p, 1);
            p += __shfl_xor_sync(0xffffffffu, p, 2);
            if ((lane & 3) == 0) attp[wn][wm * 48 + mf * 16 + g + h * 8] = p;
        }
    __syncthreads();
    if (tid < GM && r0 + tid < NROWS) {
        float a = hp_b1[0];
#pragma unroll
        for (int w = 0; w < 8; w++) a += attp[w][tid];
        g_att[r0 + tid] = a;
    }
}

// ---------------- fused g_theta (262 M=96 tiles) ----------------
// smem: A1 [0,49152) | A2h [49152,98304) | A2l [98304,147456) | B [147456,213 K)
__global__ void __launch_bounds__(512) k_gt_mma(const float* __restrict__ gt_b1) {
    extern __shared__ char sm_raw[];
    __shared__ float s_b1[256];
    __shared__ float relp[2][256];

    const int tid = threadIdx.x;
    const int r0 = blockIdx.x * GM;
    const int wid = tid >> 5, lane = tid & 31;
    const int wm = wid & 1, wn = wid >> 1;

    uint32_t raw = smem_u32(sm_raw);
    uint32_t smb = (raw + 1023u) & ~1023u;
    const uint32_t A2h = smb + 49152, A2l = smb + 98304;
    const uint32_t Bbuf = smb + 147456;

    if (tid < 256) s_b1[tid] = gt_b1[tid];
    if (tid < 512) ((float*)relp)[tid] = 0.0f;

    uint32_t rbase[3];
#pragma unroll
    for (int mf = 0; mf < 3; mf++) rbase[mf] = (uint32_t)(wm * 48 + mf * 16 + (lane & 15)) * 128;
    const uint32_t kHi = (lane >> 4) * 16;
    const uint32_t chbase = (uint32_t)((wn & 3) * 32 + (lane & 15)) * 128;
    const uint32_t Bwn = (wn >> 2) * 16384;
    const int g = lane >> 2, t2 = (lane & 3) * 2;

    float acc[3][16];
#pragma unroll
    for (int i = 0; i < 3; i++)
#pragma unroll
        for (int j = 0; j < 16; j++) acc[i][j] = 0.0f;

    {
#pragma unroll
        for (int t = 0; t < 4; t++) cp16(Bbuf + (tid + t * 512) * 16, g_gt0Bh + (tid + t * 512) * 16);
        load_A_tile96(smb, r0, tid);
        cp_commit();
    }

    for (int s = 0; s < 12; s++) {
        if (s < 11) {
            int sn = s + 1;
            const uint8_t* basep;
            int kblk;
            if (sn < 4) { basep = (sn & 1) ? g_gt0Bl : g_gt0Bh; kblk = sn >> 1; }
            else        { int t = sn - 4; basep = (t & 1) ? g_gt1Bl : g_gt1Bh; kblk = t >> 1; }
            const uint8_t* src = basep + (size_t)kblk * 32768;
            uint32_t dstb = Bbuf + (sn & 1) * 32768;
#pragma unroll
            for (int t = 0; t < 4; t++) cp16(dstb + (tid + t * 512) * 16, src + (tid + t * 512) * 16);
            cp_commit();
            asm volatile("cp.async.wait_group 1;" ::: "memory");
        } else {
            asm volatile("cp.async.wait_group 0;" ::: "memory");
        }
        __syncthreads();

        if (s < 4) {
            int kblk = s >> 1;
            gemm_stage96(acc, smb + kblk * A_ATOM, smb + 24576 + kblk * A_ATOM,
                         Bbuf + (s & 1) * 32768 + Bwn, (s & 1) == 0, rbase, chbase, kHi);
        } else {
            int kt = (s - 4) >> 1;
            gemm_stage96(acc, A2h + kt * A_ATOM, A2l + kt * A_ATOM,
                         Bbuf + (s & 1) * 32768 + Bwn, (s & 1) == 0, rbase, chbase, kHi);
        }
        __syncthreads();

        if (s == 3) {
            // g1 = relu(acc + pero + pern) -> A2 (bf16 hi/lo), reset acc
#pragma unroll
            for (int mf = 0; mf < 3; mf++)
#pragma unroll
                for (int h = 0; h < 2; h++) {
                    int row = wm * 48 + mf * 16 + g + h * 8;
                    int r = r0 + row; if (r >= NROWS) r = NROWS - 1;
                    int n = r / OO, o = r - n * OO;
#pragma unroll
                    for (int nf = 0; nf < 4; nf++) {
                        int ch0 = wn * 32 + nf * 8 + t2;
                        float v0 = acc[mf][nf * 4 + h * 2 + 0] + g_pero_gt[o * 256 + ch0]     + g_pern_gt[n * 256 + ch0];
                        float v1 = acc[mf][nf * 4 + h * 2 + 1] + g_pero_gt[o * 256 + ch0 + 1] + g_pern_gt[n * 256 + ch0 + 1];
                        v0 = fmaxf(v0, 0.0f); v1 = fmaxf(v1, 0.0f);
                        __nv_bfloat16 h0, l0, h1, l1;
                        bf16split(v0, h0, l0);
                        bf16split(v1, h1, l1);
                        uint32_t off = (uint32_t)(ch0 >> 6) * A_ATOM + SWZ(row * 128 + (ch0 & 63) * 2);
                        *(__nv_bfloat162*)(sm_raw + (A2h - raw) + off) = __nv_bfloat162{h0, h1};
                        *(__nv_bfloat162*)(sm_raw + (A2l - raw) + off) = __nv_bfloat162{l0, l1};
                    }
                }
#pragma unroll
            for (int i = 0; i < 3; i++)
#pragma unroll
                for (int j = 0; j < 16; j++) acc[i][j] = 0.0f;
            __syncthreads();
        }
    }

    // epilogue: relu(g2 + b1), per-n partial sums (tile spans <=2 images)
    int rlast = r0 + GM - 1; if (rlast >= NROWS) rlast = NROWS - 1;
    const int n0 = r0 / OO;
    const int n1 = rlast / OO;
#pragma unroll
    for (int mf = 0; mf < 3; mf++)
#pragma unroll
        for (int h = 0; h < 2; h++) {
            int row = wm * 48 + mf * 16 + g + h * 8;
            int r = r0 + row;
            if (r < NROWS) {
                int n = r / OO;
                int nn = (n != n0);
#pragma unroll
                for (int nf = 0; nf < 4; nf++)
#pragma unroll
                    for (int j = 0; j < 2; j++) {
                        int ch = wn * 32 + nf * 8 + t2 + j;
                        float v = fmaxf(acc[mf][nf * 4 + h * 2 + j] + s_b1[ch], 0.0f);
                        atomicAdd(&relp[nn][ch], v);
                    }
            }
        }
    __syncthreads();
    if (tid < 256) {
        atomicAdd(&g_rel[n0 * 256 + tid], relp[0][tid]);
    } else {
        int ch = tid - 256;
        if (n1 != n0) atomicAdd(&g_rel[n1 * 256 + ch], relp[1][ch]);
    }
}

// ---------------- softmax + soft selection + pern_gt finish (round-12, passing) ----------------
__global__ void __launch_bounds__(512) k_softsel(const float* __restrict__ gt_w0) {
    int n = blockIdx.x;
    int tid = threadIdx.x;
    __shared__ float att_s[OO];
    __shared__ float red_s[16];
    __shared__ float selp[4][128];
    __shared__ float sel_s[CED];
    __shared__ float pgp[2][256];

    if (tid < OO) att_s[tid] = g_att[n * OO + tid];
    __syncthreads();

    float v = (tid < OO) ? att_s[tid] : -1e30f;
#pragma unroll
    for (int off = 16; off > 0; off >>= 1) v = fmaxf(v, __shfl_xor_sync(0xffffffffu, v, off));
    if ((tid & 31) == 0) red_s[tid >> 5] = v;
    __syncthreads();
    float m = -1e30f;
#pragma unroll
    for (int i = 0; i < 16; i++) m = fmaxf(m, red_s[i]);
    __syncthreads();

    float e = (tid < OO) ? expf(att_s[tid] - m) : 0.0f;
    float sv = e;
#pragma unroll
    for (int off = 16; off > 0; off >>= 1) sv += __shfl_xor_sync(0xffffffffu, sv, off);
    if ((tid & 31) == 0) red_s[tid >> 5] = sv;
    __syncthreads();
    float tot = 0.0f;
#pragma unroll
    for (int i = 0; i < 16; i++) tot += red_s[i];
    if (tid < OO) att_s[tid] = e / tot;
    __syncthreads();

    {
        const float* xtn = g_xt + (size_t)n * OO * CF;
        int q = tid >> 7, d = tid & 127;
        int o0 = q * 49;
        float a[8];
#pragma unroll
        for (int k = 0; k < 8; k++) a[k] = 0.0f;
#pragma unroll
        for (int i = 0; i < 48; i += 8) {
#pragma unroll
            for (int k = 0; k < 8; k++)
                a[k] = fmaf(att_s[o0 + i + k], xtn[(size_t)(o0 + i + k) * CF + d], a[k]);
        }
        a[0] = fmaf(att_s[o0 + 48], xtn[(size_t)(o0 + 48) * CF + d], a[0]);
        selp[q][d] = ((a[0] + a[1]) + (a[2] + a[3])) + ((a[4] + a[5]) + (a[6] + a[7]));
    }
    __syncthreads();
    if (tid < 128) {
        float s = (selp[0][tid] + selp[1][tid]) + (selp[2][tid] + selp[3][tid]);
        g_sel[n * CED + tid] = s;
        sel_s[tid] = s;
    } else if (tid == 128) {
        float a = 0.0f;
        for (int o = 0; o < OO; o++) a = fmaf(att_s[o], xcoord(o), a);
        g_sel[n * CED + 128] = a;
        sel_s[128] = a;
    } else if (tid == 129) {
        float a = 0.0f;
        for (int o = 0; o < OO; o++) a = fmaf(att_s[o], ycoord(o), a);
        g_sel[n * CED + 129] = a;
        sel_s[129] = a;
    }
    __syncthreads();

    {
        int p = tid >> 8, ch = tid & 255;
        int d0 = p * 65, d1 = d0 + 65;
        float s = 0.0f;
#pragma unroll 4
        for (int d = d0; d < d1; d++)
            s = fmaf(sel_s[d], gt_w0[(QD + d) * 256 + ch], s);
        pgp[p][ch] = s;
    }
    __syncthreads();
    if (tid < 256)
        g_pern_gt[n * 256 + tid] += pgp[0][tid] + pgp[1][tid];
}

// ---------------- f_phi head ----------------
__global__ void __launch_bounds__(256) k_fphi(const float* __restrict__ fp_w0,
                                              const float* __restrict__ fp_b0,
                                              const float* __restrict__ fp_w1,
                                              const float* __restrict__ fp_b1,
                                              float* __restrict__ out) {
    int n = blockIdx.x;
    int tid = threadIdx.x;
    __shared__ float f_s[FP];

    const float* rel = g_rel + n * GT;
    float s = fp_b0[tid];
#pragma unroll 4
    for (int h = 0; h < GT; h++)
        s = fmaf(rel[h], fp_w0[h * FP + tid], s);
    f_s[tid] = fmaxf(s, 0.0f);
    __syncthreads();

    if (tid < ASZ) {
        float s2 = fp_b1[tid];
#pragma unroll 4
        for (int h = 0; h < FP; h++)
            s2 = fmaf(f_s[h], fp_w1[h * ASZ + tid], s2);
        out[n * ASZ + tid] = s2;
    }
}

// ---------------- launch ----------------
extern "C" void kernel_launch(void* const* d_in, const int* in_sizes, int n_in,
                              void* d_out, int out_size) {
    const float* image  = (const float*)d_in[0];
    const float* code   = (const float*)d_in[1];
    const float* conv_w = (const float*)d_in[2];
    const float* conv_b = (const float*)d_in[3];
    const float* hp_w0  = (const float*)d_in[4];
    const float* hp_b0  = (const float*)d_in[5];
    const float* hp_w1  = (const float*)d_in[6];
    const float* hp_b1  = (const float*)d_in[7];
    const float* gt_w0  = (const float*)d_in[8];
    const float* gt_b0  = (const float*)d_in[9];
    const float* gt_w1  = (const float*)d_in[10];
    const float* gt_b1  = (const float*)d_in[11];
    const float* fp_w0  = (const float*)d_in[12];
    const float* fp_b0  = (const float*)d_in[13];
    const float* fp_w1  = (const float*)d_in[14];
    const float* fp_b1  = (const float*)d_in[15];
    float* out = (float*)d_out;

    cudaFuncSetAttribute(k_conv_mma, cudaFuncAttributeMaxDynamicSharedMemorySize, CONV_SMEM);
    cudaFuncSetAttribute(k_hpsi_mma, cudaFuncAttributeMaxDynamicSharedMemorySize, 115712);
    cudaFuncSetAttribute(k_gt_mma,   cudaFuncAttributeMaxDynamicSharedMemorySize, 214016);

    k_prep_all<<<PREP_BLOCKS, 256>>>(image, conv_w, code, hp_w0, hp_b0, gt_w0, gt_b0, gt_w1);
    k_conv_mma<<<NCTA, 512, CONV_SMEM>>>(conv_b);
    k_hpsi_mma<<<NT96, 512, 115712>>>(hp_w1, hp_b1);
    k_softsel<<<NB, 512>>>(gt_w0);
    k_gt_mma<<<NT96, 512, 214016>>>(gt_b1);
    k_fphi<<<NB, 256>>>(fp_w0, fp_b0, fp_w1, fp_b1, out);
}

// round 16
// speedup vs baseline: 1.2957x; 1.0341x over previous
#include <cuda_runtime.h>
#include <cuda_bf16.h>
#include <cstdint>

// ---------------- problem constants ----------------
#define NB    128
#define CIN   1024
#define HH    14
#define WW    14
#define OO    196
#define CF    128
#define TH    128
#define QD    258
#define CED   130
#define PD    388
#define HP    256
#define GT    256
#define FP    256
#define ASZ   32
#define NROWS (NB * OO)     // 25088

// ---------------- scratch ----------------
// NOTE: g_imh/g_iml halo borders rely on CUDA zero-initialization of __device__
// globals; k_prep_all writes interior cells only, nothing ever writes borders.
__device__ __align__(16) __nv_bfloat16 g_imh[NB * 256 * CIN];
__device__ __align__(16) __nv_bfloat16 g_iml[NB * 256 * CIN];
__device__ __align__(16) uint8_t g_wbh[144 * 16384];
__device__ __align__(16) uint8_t g_wbl[144 * 16384];
__device__ __align__(16) float g_xt[NB * OO * CF];
__device__ __align__(16) __nv_bfloat16 g_xth[NB * OO * CF];
__device__ __align__(16) __nv_bfloat16 g_xtl[NB * OO * CF];
__device__ __align__(16) uint8_t g_hpBh[4 * 16384],  g_hpBl[4 * 16384];
__device__ __align__(16) uint8_t g_gt0Bh[4 * 16384], g_gt0Bl[4 * 16384];
__device__ __align__(16) uint8_t g_gt1Bh[8 * 16384], g_gt1Bl[8 * 16384];
__device__ float g_pero_hp[OO * 256], g_pern_hp[NB * 256];
__device__ float g_pero_gt[OO * 256], g_pern_gt[NB * 256];
__device__ float g_att[NB * OO];
__device__ float g_sel[NB * CED];
__device__ float g_rel[NB * GT];

__device__ __forceinline__ float xcoord(int o) { return -1.0f + 2.0f * (float)(o / WW) / 13.0f; }
__device__ __forceinline__ float ycoord(int o) { return -1.0f + 2.0f * (float)(o % WW) / 13.0f; }

// ---------------- helpers ----------------
#define SWZ(x) ((x) ^ (((x) >> 3) & 0x70))

__device__ __forceinline__ uint32_t smem_u32(const void* p) {
    uint32_t a;
    asm("{ .reg .u64 t; cvta.to.shared.u64 t, %1; cvt.u32.u64 %0, t; }" : "=r"(a) : "l"(p));
    return a;
}
__device__ __forceinline__ void ldsm_x4(uint32_t* r, uint32_t addr) {
    asm volatile("ldmatrix.sync.aligned.m8n8.x4.shared.b16 {%0,%1,%2,%3}, [%4];"
                 : "=r"(r[0]), "=r"(r[1]), "=r"(r[2]), "=r"(r[3]) : "r"(addr));
}
__device__ __forceinline__ void mma16816(float* c, const uint32_t* a, uint32_t b0, uint32_t b1) {
    asm volatile("mma.sync.aligned.m16n8k16.row.col.f32.bf16.bf16.f32 "
                 "{%0,%1,%2,%3}, {%4,%5,%6,%7}, {%8,%9}, {%0,%1,%2,%3};"
                 : "+f"(c[0]), "+f"(c[1]), "+f"(c[2]), "+f"(c[3])
                 : "r"(a[0]), "r"(a[1]), "r"(a[2]), "r"(a[3]), "r"(b0), "r"(b1));
}
__device__ __forceinline__ void cp16(uint32_t dst, const void* src) {
    asm volatile("cp.async.cg.shared.global [%0], [%1], 16;" :: "r"(dst), "l"(src));
}
__device__ __forceinline__ void cp_commit() { asm volatile("cp.async.commit_group;" ::: "memory"); }
__device__ __forceinline__ void bf16split(float v, __nv_bfloat16& h, __nv_bfloat16& l) {
    h = __float2bfloat16(v);
    l = __float2bfloat16(v - __bfloat162float(h));
}

// ---------------- mega prep kernel ----------------
#define PREP_BLOCKS 19780

__device__ __forceinline__ void mlppack_one(const float* __restrict__ src,
                                            uint8_t* __restrict__ dstH,
                                            uint8_t* __restrict__ dstL, int idx) {
    int k6    = idx & 63;
    int ch    = (idx >> 6) & 127;
    int chblk = (idx >> 13) & 1;
    int kblk  = idx >> 14;
    float v = src[(kblk * 64 + k6) * 256 + chblk * 128 + ch];
    __nv_bfloat16 hi, lo; bf16split(v, hi, lo);
    int off = (kblk * 2 + chblk) * 16384 + SWZ(ch * 128 + k6 * 2);
    *(__nv_bfloat16*)(dstH + off) = hi;
    *(__nv_bfloat16*)(dstL + off) = lo;
}

__global__ void __launch_bounds__(256) k_prep_all(
    const float* __restrict__ image, const float* __restrict__ conv_w,
    const float* __restrict__ code,
    const float* __restrict__ hp_w0, const float* __restrict__ hp_b0,
    const float* __restrict__ gt_w0, const float* __restrict__ gt_b0,
    const float* __restrict__ gt_w1)
{
    int b = blockIdx.x, tid = threadIdx.x;

    if (b < 4608) {
        int idx = b * 256 + tid;
        int j    = idx & 63;
        int ch   = (idx >> 6) & 127;
        int cb   = (idx >> 13) & 15;
        int kykx = idx >> 17;
        int cin  = cb * 64 + j;
        float v = conv_w[ch * (CIN * 9) + cin * 9 + kykx];
        __nv_bfloat16 hi, lo; bf16split(v, hi, lo);
        int dst = (kykx * 16 + cb) * 16384 + SWZ(ch * 128 + j * 2);
        *(__nv_bfloat16*)(g_wbh + dst) = hi;
        *(__nv_bfloat16*)(g_wbl + dst) = lo;
    } else if (b < 4736) {
        mlppack_one(hp_w0, g_hpBh, g_hpBl, (b - 4608) * 256 + tid);
    } else if (b < 4864) {
        mlppack_one(gt_w0, g_gt0Bh, g_gt0Bl, (b - 4736) * 256 + tid);
    } else if (b < 5120) {
        mlppack_one(gt_w1, g_gt1Bh, g_gt1Bl, (b - 4864) * 256 + tid);
    } else if (b < 19456) {
        int bb = b - 5120;
        int pb = bb % 7, cbk = (bb / 7) % 16, n = bb / 112;
        __shared__ float t[64][33];
        int pos0 = pb * 32;
        for (int e = tid; e < 64 * 32; e += 256) {
            int ci = e >> 5, p = e & 31;
            int pos = pos0 + p;
            float v = 0.0f;
            if (pos < OO) v = image[((size_t)n * CIN + cbk * 64 + ci) * OO + pos];
            t[ci][p] = v;
        }
        __syncthreads();
        for (int e = tid; e < 64 * 32; e += 256) {
            int p = e >> 6, ci = e & 63;
            int pos = pos0 + p;
            if (pos < OO) {
                int row = pos / 14, col = pos - row * 14;
                int hp  = (row + 1) * 16 + (col + 1);
                size_t off = ((size_t)n * 256 + hp) * 1024 + cbk * 64 + ci;
                __nv_bfloat16 hi, lo; bf16split(t[ci][p], hi, lo);
                g_imh[off] = hi;
                g_iml[off] = lo;
            }
        }
    } else if (b < 19652) {
        int o = b - 19456, ch = tid;
        float xc = xcoord(o), yc = ycoord(o);
        g_pero_hp[o * 256 + ch] = xc * hp_w0[128 * 256 + ch] + yc * hp_w0[129 * 256 + ch];
        g_pero_gt[o * 256 + ch] = xc * gt_w0[128 * 256 + ch] + yc * gt_w0[129 * 256 + ch];
    } else {
        int n = b - 19652, ch = tid;
        float sh = hp_b0[ch], sg = gt_b0[ch];
#pragma unroll 4
        for (int d = 0; d < 128; d++) {
            float c = code[n * 128 + d];
            sh = fmaf(c, hp_w0[(130 + d) * 256 + ch], sh);
            sg = fmaf(c, gt_w0[(130 + d) * 256 + ch], sg);
        }
        g_pern_hp[n * 256 + ch] = sh;
        g_pern_gt[n * 256 + ch] = sg;
        g_rel[n * 256 + ch] = 0.0f;
    }
}

// ---------------- conv: global-row unit split (zero padding), 148 CTAs, one wave ----------------
// 25088 rows = exactly 1568 units of 16. CTA i owns units [i*1568/148, (i+1)*1568/148) = 10-11,
// row span <= 176 < 196 -> <= 2 images. Units may straddle image boundaries; ldsm per-lane
// addressing selects halo slot + position per lane (slot folded into pbA as slot*512 positions).
// smem: haloA(H32K,L32K) haloB(H32K,L32K) | B 2x32K = 192KB + 1K pad.
#define NUNITS 1568
#define NCTA   148
#define CONV_SMEM 197632

__device__ __forceinline__ void prefetch_B2(int g, uint32_t Bb, int tid) {
    int cb = g / 9, kykx = g - cb * 9;
    size_t off = (size_t)(kykx * 16 + cb) * 16384;
    uint32_t dst = Bb + (uint32_t)(g & 1) * 32768;
#pragma unroll
    for (int t = 0; t < 2; t++) {
        int i = tid + t * 512;
        cp16(dst + i * 16,         g_wbh + off + i * 16);
        cp16(dst + 16384 + i * 16, g_wbl + off + i * 16);
    }
}

template<int NMF>
__device__ __forceinline__ void conv_stage(uint32_t haloH, uint32_t haloL, uint32_t Bstage,
                                           int kd, const int* pbA, int chB0, int kHi,
                                           float (*acc)[16]) {
    uint32_t Bh = Bstage, Bl = Bstage + 16384;
#pragma unroll
    for (int ks = 0; ks < 4; ks++) {
        uint32_t bh[2][4], bl[2][4], a[NMF][4];
        uint32_t kof = (uint32_t)(ks * 32 + kHi);
#pragma unroll
        for (int bf = 0; bf < 2; bf++) ldsm_x4(bh[bf], Bh + SWZ((uint32_t)((chB0 + bf * 16) * 128) + kof));
#pragma unroll
        for (int mf = 0; mf < NMF; mf++) ldsm_x4(a[mf], haloH + SWZ((uint32_t)((pbA[mf] + kd) * 128) + kof));
#pragma unroll
        for (int mf = 0; mf < NMF; mf++)
#pragma unroll
            for (int nf = 0; nf < 4; nf++)
                mma16816(&acc[mf][nf * 4], a[mf], bh[nf >> 1][nf & 1], bh[nf >> 1][(nf & 1) + 2]);
#pragma unroll
        for (int bf = 0; bf < 2; bf++) ldsm_x4(bl[bf], Bl + SWZ((uint32_t)((chB0 + bf * 16) * 128) + kof));
#pragma unroll
        for (int mf = 0; mf < NMF; mf++)
#pragma unroll
            for (int nf = 0; nf < 4; nf++)
                mma16816(&acc[mf][nf * 4], a[mf], bl[nf >> 1][nf & 1], bl[nf >> 1][(nf & 1) + 2]);
#pragma unroll
        for (int mf = 0; mf < NMF; mf++) ldsm_x4(a[mf], haloL + SWZ((uint32_t)((pbA[mf] + kd) * 128) + kof));
#pragma unroll
        for (int mf = 0; mf < NMF; mf++)
#pragma unroll
            for (int nf = 0; nf < 4; nf++)
                mma16816(&acc[mf][nf * 4], a[mf], bh[nf >> 1][nf & 1], bh[nf >> 1][(nf & 1) + 2]);
    }
}

// haloH layout: slot0 H at [0,32K), slot1 H at [64K,96K); haloL: slot0 L at [32K,64K), slot1 L at [96K,128K)
// pbA carries slot*512 positions (= slot*65536 bytes); haloL base = haloH base + 32768.
__device__ __forceinline__ void load_halo(char* sm, int slot, int img, int cb, int tid) {
#pragma unroll
    for (int t = 0; t < 8; t++) {
        int idx = tid + t * 512;
        int half = idx >> 11;
        int j = idx & 2047;
        int p = j >> 3, u = j & 7;
        const __nv_bfloat16* srcp = (half ? g_iml : g_imh) + ((size_t)img * 256 + p) * 1024 + cb * 64;
        uint4 v = ((const uint4*)srcp)[u];
        *(uint4*)(sm + slot * 65536 + half * 32768 + SWZ(p * 128 + u * 16)) = v;
    }
}

__global__ void __launch_bounds__(512) k_conv_mma(const float* __restrict__ conv_b) {
    extern __shared__ char sm_raw[];
    __shared__ float s_bias[128];
    const int tid = threadIdx.x;
    const int wid = tid >> 5, lane = tid & 31;
    const int wm = wid >> 2, wn = wid & 3;

    const int u0 = (blockIdx.x * NUNITS) / NCTA;
    const int u1 = ((blockIdx.x + 1) * NUNITS) / NCTA;
    const int cnt = u1 - u0;                 // 10 or 11
    const int n0 = (u0 * 16) / OO;
    const int n1 = (u1 * 16 - 1) / OO;
    const int two = (n1 != n0);
    const int nmf = (cnt - wm + 3) >> 2;     // units: u0 + wm + 4*mf

    uint32_t raw = smem_u32(sm_raw);
    uint32_t base = (raw + 1023u) & ~1023u;
    char* sm = sm_raw + (base - raw);
    const uint32_t Bb = base + 131072;

    if (tid < 128) s_bias[tid] = conv_b[tid];

    float acc[3][16];
#pragma unroll
    for (int i = 0; i < 3; i++)
#pragma unroll
        for (int j = 0; j < 16; j++) acc[i][j] = 0.0f;

    int pbA[3], uG[3];
#pragma unroll
    for (int mf = 0; mf < 3; mf++) {
        int uu = u0 + wm + 4 * mf;
        if (uu >= u1) uu = u1 - 1;           // clamp (unused slots only)
        uG[mf] = uu;
        int r = uu * 16 + (lane & 15);       // global row, always < NROWS
        int nn = r / OO, oo = r - nn * OO;
        int row = oo / 14, col = oo - row * 14;
        pbA[mf] = (nn - n0) * 512 + row * 16 + col;   // slot folded into position
    }
    const int kHi = (lane >> 4) * 16;
    const int chB0 = wn * 32 + (lane & 15);

    prefetch_B2(0, Bb, tid); cp_commit();

    for (int gs = 0; gs < 144; gs++) {
        int cb = gs / 9, kykx = gs - cb * 9;
        if (kykx == 0) {
            __syncthreads();                 // old halo reads done
            load_halo(sm, 0, n0, cb, tid);
            if (two) load_halo(sm, 1, n1, cb, tid);
        }
        if (gs + 1 < 144) {
            prefetch_B2(gs + 1, Bb, tid);
            cp_commit();
            asm volatile("cp.async.wait_group 1;" ::: "memory");
        } else {
            asm volatile("cp.async.wait_group 0;" ::: "memory");
        }
        __syncthreads();                     // publish B(gs) + halo

        int ky = kykx / 3, kx = kykx - ky * 3;
        int kd = ky * 16 + kx;
        uint32_t Bst = Bb + (uint32_t)(gs & 1) * 32768;

        if (nmf == 3) conv_stage<3>(base, base + 32768, Bst, kd, pbA, chB0, kHi, acc);
        else          conv_stage<2>(base, base + 32768, Bst, kd, pbA, chB0, kHi, acc);
        __syncthreads();                     // B(gs) reads done before overwrite
    }

    int g = lane >> 2, t2 = (lane & 3) * 2;
#pragma unroll
    for (int mf = 0; mf < 3; mf++) {
        if (mf < nmf) {
#pragma unroll
            for (int nf = 0; nf < 4; nf++) {
                int ch = wn * 32 + nf * 8 + t2;
                float b0 = s_bias[ch], b1 = s_bias[ch + 1];
#pragma unroll
                for (int h = 0; h < 2; h++) {
                    int r = uG[mf] * 16 + g + h * 8;     // always < NROWS
                    float v0 = acc[mf][nf * 4 + h * 2 + 0] + b0;
                    float v1 = acc[mf][nf * 4 + h * 2 + 1] + b1;
                    g_xt[(size_t)r * CF + ch]     = v0;
                    g_xt[(size_t)r * CF + ch + 1] = v1;
                    __nv_bfloat16 h0, l0, h1, l1;
                    bf16split(v0, h0, l0);
                    bf16split(v1, h1, l1);
                    *(__nv_bfloat162*)(g_xth + (size_t)r * CF + ch) = __nv_bfloat162{h0, h1};
                    *(__nv_bfloat162*)(g_xtl + (size_t)r * CF + ch) = __nv_bfloat162{l0, l1};
                }
            }
        }
    }
}

// ---------------- M=96 GEMM machinery (262 tiles; 2M x 8N warps, mf<3) ----------------
#define GM    96
#define NT96  262
#define A_ATOM 12288

__device__ __forceinline__ void gemm_stage96(float (*acc)[16], uint32_t AhT, uint32_t AlT,
                                             uint32_t Bt, bool doLo,
                                             const uint32_t* rbase, uint32_t chbase, uint32_t kHi) {
#pragma unroll
    for (int ks = 0; ks < 4; ks++) {
        uint32_t b[2][4];
        ldsm_x4(b[0], Bt + SWZ(chbase + ks * 32 + kHi));
        ldsm_x4(b[1], Bt + SWZ(chbase + 16 * 128 + ks * 32 + kHi));
#pragma unroll
        for (int mf = 0; mf < 3; mf++) {
            uint32_t a[4];
            ldsm_x4(a, AhT + SWZ(rbase[mf] + ks * 32 + kHi));
#pragma unroll
            for (int nf = 0; nf < 4; nf++)
                mma16816(&acc[mf][nf * 4], a,
                         (nf & 1) ? b[nf >> 1][1] : b[nf >> 1][0],
                         (nf & 1) ? b[nf >> 1][3] : b[nf >> 1][2]);
            if (doLo) {
                uint32_t al[4];
                ldsm_x4(al, AlT + SWZ(rbase[mf] + ks * 32 + kHi));
#pragma unroll
                for (int nf = 0; nf < 4; nf++)
                    mma16816(&acc[mf][nf * 4], al,
                             (nf & 1) ? b[nf >> 1][1] : b[nf >> 1][0],
                             (nf & 1) ? b[nf >> 1][3] : b[nf >> 1][2]);
            }
        }
    }
}

__device__ __forceinline__ void load_A_tile96(uint32_t smb, int r0, int tid) {
#pragma unroll
    for (int t = 0; t < 6; t++) {
        int idx = tid + t * 512;
        int half = idx >= 1536;
        int j = idx - half * 1536;
        int row = j >> 4, cc = j & 15;
        int kblk = cc >> 3, u = cc & 7;
        int rr = r0 + row; if (rr >= NROWS) rr = NROWS - 1;
        const __nv_bfloat16* src = (half ? g_xtl : g_xth) + (size_t)rr * 128 + kblk * 64 + u * 8;
        cp16(smb + half * 24576 + kblk * A_ATOM + SWZ(row * 128 + u * 16), src);
    }
}

// ---------------- h_psi as GEMM (262 M=96 tiles) ----------------
__global__ void __launch_bounds__(512) k_hpsi_mma(const float* __restrict__ hp_w1,
                                                  const float* __restrict__ hp_b1) {
    extern __shared__ char sm_raw[];
    __shared__ float s_w1[256];
    __shared__ float attp[8][GM];

    const int tid = threadIdx.x;
    const int r0 = blockIdx.x * GM;
    const int wid = tid >> 5, lane = tid & 31;
    const int wm = wid & 1, wn = wid >> 1;

    uint32_t raw = smem_u32(sm_raw);
    uint32_t smb = (raw + 1023u) & ~1023u;
    const uint32_t Bbuf = smb + 49152;

    if (tid < 256) s_w1[tid] = hp_w1[tid];

    uint32_t rbase[3];
#pragma unroll
    for (int mf = 0; mf < 3; mf++) rbase[mf] = (uint32_t)(wm * 48 + mf * 16 + (lane & 15)) * 128;
    const uint32_t kHi = (lane >> 4) * 16;
    const uint32_t chbase = (uint32_t)((wn & 3) * 32 + (lane & 15)) * 128;
    const uint32_t Bwn = (wn >> 2) * 16384;

    float acc[3][16];
#pragma unroll
    for (int i = 0; i < 3; i++)
#pragma unroll
        for (int j = 0; j < 16; j++) acc[i][j] = 0.0f;

    {
        const uint8_t* src = g_hpBh;
#pragma unroll
        for (int t = 0; t < 4; t++) cp16(Bbuf + (tid + t * 512) * 16, src + (tid + t * 512) * 16);
        load_A_tile96(smb, r0, tid);
        cp_commit();
    }

    for (int s = 0; s < 4; s++) {
        if (s < 3) {
            int sn = s + 1;
            const uint8_t* src = ((sn & 1) ? g_hpBl : g_hpBh) + (size_t)(sn >> 1) * 32768;
            uint32_t dstb = Bbuf + (sn & 1) * 32768;
#pragma unroll
            for (int t = 0; t < 4; t++) cp16(dstb + (tid + t * 512) * 16, src + (tid + t * 512) * 16);
            cp_commit();
            asm volatile("cp.async.wait_group 1;" ::: "memory");
        } else {
            asm volatile("cp.async.wait_group 0;" ::: "memory");
        }
        __syncthreads();
        int kblk = s >> 1;
        gemm_stage96(acc, smb + kblk * A_ATOM, smb + 24576 + kblk * A_ATOM,
                     Bbuf + (s & 1) * 32768 + Bwn, (s & 1) == 0, rbase, chbase, kHi);
        __syncthreads();
    }

    int g = lane >> 2, t2 = (lane & 3) * 2;
    float psum[3][2];
#pragma unroll
    for (int mf = 0; mf < 3; mf++) { psum[mf][0] = 0.0f; psum[mf][1] = 0.0f; }
#pragma unroll
    for (int mf = 0; mf < 3; mf++)
#pragma unroll
        for (int h = 0; h < 2; h++) {
            int row = wm * 48 + mf * 16 + g + h * 8;
            int r = r0 + row; if (r >= NROWS) r = NROWS - 1;
            int n = r / OO, o = r - n * OO;
#pragma unroll
            for (int nf = 0; nf < 4; nf++)
#pragma unroll
                for (int j = 0; j < 2; j++) {
                    int ch = wn * 32 + nf * 8 + t2 + j;
                    float v = acc[mf][nf * 4 + h * 2 + j] + g_pero_hp[o * 256 + ch] + g_pern_hp[n * 256 + ch];
                    psum[mf][h] += fmaxf(v, 0.0f) * s_w1[ch];
                }
        }
#pragma unroll
    for (int mf = 0; mf < 3; mf++)
#pragma unroll
        for (int h = 0; h < 2; h++) {
            float p = psum[mf][h];
            p += __shfl_xor_sync(0xffffffffu, p, 1);
            p += __shfl_xor_sync(0xffffffffu, p, 2);
            if ((lane & 3) == 0) attp[wn][wm * 48 + mf * 16 + g + h * 8] = p;
        }
    __syncthreads();
    if (tid < GM && r0 + tid < NROWS) {
        float a = hp_b1[0];
#pragma unroll
        for (int w = 0; w < 8; w++) a += attp[w][tid];
        g_att[r0 + tid] = a;
    }
}

// ---------------- fused g_theta (262 M=96 tiles) ----------------
__global__ void __launch_bounds__(512) k_gt_mma(const float* __restrict__ gt_b1) {
    extern __shared__ char sm_raw[];
    __shared__ float s_b1[256];
    __shared__ float relp[2][256];

    const int tid = threadIdx.x;
    const int r0 = blockIdx.x * GM;
    const int wid = tid >> 5, lane = tid & 31;
    const int wm = wid & 1, wn = wid >> 1;

    uint32_t raw = smem_u32(sm_raw);
    uint32_t smb = (raw + 1023u) & ~1023u;
    const uint32_t A2h = smb + 49152, A2l = smb + 98304;
    const uint32_t Bbuf = smb + 147456;

    if (tid < 256) s_b1[tid] = gt_b1[tid];
    if (tid < 512) ((float*)relp)[tid] = 0.0f;

    uint32_t rbase[3];
#pragma unroll
    for (int mf = 0; mf < 3; mf++) rbase[mf] = (uint32_t)(wm * 48 + mf * 16 + (lane & 15)) * 128;
    const uint32_t kHi = (lane >> 4) * 16;
    const uint32_t chbase = (uint32_t)((wn & 3) * 32 + (lane & 15)) * 128;
    const uint32_t Bwn = (wn >> 2) * 16384;
    const int g = lane >> 2, t2 = (lane & 3) * 2;

    float acc[3][16];
#pragma unroll
    for (int i = 0; i < 3; i++)
#pragma unroll
        for (int j = 0; j < 16; j++) acc[i][j] = 0.0f;

    {
#pragma unroll
        for (int t = 0; t < 4; t++) cp16(Bbuf + (tid + t * 512) * 16, g_gt0Bh + (tid + t * 512) * 16);
        load_A_tile96(smb, r0, tid);
        cp_commit();
    }

    for (int s = 0; s < 12; s++) {
        if (s < 11) {
            int sn = s + 1;
            const uint8_t* basep;
            int kblk;
            if (sn < 4) { basep = (sn & 1) ? g_gt0Bl : g_gt0Bh; kblk = sn >> 1; }
            else        { int t = sn - 4; basep = (t & 1) ? g_gt1Bl : g_gt1Bh; kblk = t >> 1; }
            const uint8_t* src = basep + (size_t)kblk * 32768;
            uint32_t dstb = Bbuf + (sn & 1) * 32768;
#pragma unroll
            for (int t = 0; t < 4; t++) cp16(dstb + (tid + t * 512) * 16, src + (tid + t * 512) * 16);
            cp_commit();
            asm volatile("cp.async.wait_group 1;" ::: "memory");
        } else {
            asm volatile("cp.async.wait_group 0;" ::: "memory");
        }
        __syncthreads();

        if (s < 4) {
            int kblk = s >> 1;
            gemm_stage96(acc, smb + kblk * A_ATOM, smb + 24576 + kblk * A_ATOM,
                         Bbuf + (s & 1) * 32768 + Bwn, (s & 1) == 0, rbase, chbase, kHi);
        } else {
            int kt = (s - 4) >> 1;
            gemm_stage96(acc, A2h + kt * A_ATOM, A2l + kt * A_ATOM,
                         Bbuf + (s & 1) * 32768 + Bwn, (s & 1) == 0, rbase, chbase, kHi);
        }
        __syncthreads();

        if (s == 3) {
#pragma unroll
            for (int mf = 0; mf < 3; mf++)
#pragma unroll
                for (int h = 0; h < 2; h++) {
                    int row = wm * 48 + mf * 16 + g + h * 8;
                    int r = r0 + row; if (r >= NROWS) r = NROWS - 1;
                    int n = r / OO, o = r - n * OO;
#pragma unroll
                    for (int nf = 0; nf < 4; nf++) {
                        int ch0 = wn * 32 + nf * 8 + t2;
                        float v0 = acc[mf][nf * 4 + h * 2 + 0] + g_pero_gt[o * 256 + ch0]     + g_pern_gt[n * 256 + ch0];
                        float v1 = acc[mf][nf * 4 + h * 2 + 1] + g_pero_gt[o * 256 + ch0 + 1] + g_pern_gt[n * 256 + ch0 + 1];
                        v0 = fmaxf(v0, 0.0f); v1 = fmaxf(v1, 0.0f);
                        __nv_bfloat16 h0, l0, h1, l1;
                        bf16split(v0, h0, l0);
                        bf16split(v1, h1, l1);
                        uint32_t off = (uint32_t)(ch0 >> 6) * A_ATOM + SWZ(row * 128 + (ch0 & 63) * 2);
                        *(__nv_bfloat162*)(sm_raw + (A2h - raw) + off) = __nv_bfloat162{h0, h1};
                        *(__nv_bfloat162*)(sm_raw + (A2l - raw) + off) = __nv_bfloat162{l0, l1};
                    }
                }
#pragma unroll
            for (int i = 0; i < 3; i++)
#pragma unroll
                for (int j = 0; j < 16; j++) acc[i][j] = 0.0f;
            __syncthreads();
        }
    }

    int rlast = r0 + GM - 1; if (rlast >= NROWS) rlast = NROWS - 1;
    const int n0 = r0 / OO;
    const int n1 = rlast / OO;
#pragma unroll
    for (int mf = 0; mf < 3; mf++)
#pragma unroll
        for (int h = 0; h < 2; h++) {
            int row = wm * 48 + mf * 16 + g + h * 8;
            int r = r0 + row;
            if (r < NROWS) {
                int n = r / OO;
                int nn = (n != n0);
#pragma unroll
                for (int nf = 0; nf < 4; nf++)
#pragma unroll
                    for (int j = 0; j < 2; j++) {
                        int ch = wn * 32 + nf * 8 + t2 + j;
                        float v = fmaxf(acc[mf][nf * 4 + h * 2 + j] + s_b1[ch], 0.0f);
                        atomicAdd(&relp[nn][ch], v);
                    }
            }
        }
    __syncthreads();
    if (tid < 256) {
        atomicAdd(&g_rel[n0 * 256 + tid], relp[0][tid]);
    } else {
        int ch = tid - 256;
        if (n1 != n0) atomicAdd(&g_rel[n1 * 256 + ch], relp[1][ch]);
    }
}

// ---------------- softmax + soft selection + pern_gt finish ----------------
__global__ void __launch_bounds__(512) k_softsel(const float* __restrict__ gt_w0) {
    int n = blockIdx.x;
    int tid = threadIdx.x;
    __shared__ float att_s[OO];
    __shared__ float red_s[16];
    __shared__ float selp[4][128];
    __shared__ float sel_s[CED];
    __shared__ float pgp[2][256];

    if (tid < OO) att_s[tid] = g_att[n * OO + tid];
    __syncthreads();

    float v = (tid < OO) ? att_s[tid] : -1e30f;
#pragma unroll
    for (int off = 16; off > 0; off >>= 1) v = fmaxf(v, __shfl_xor_sync(0xffffffffu, v, off));
    if ((tid & 31) == 0) red_s[tid >> 5] = v;
    __syncthreads();
    float m = -1e30f;
#pragma unroll
    for (int i = 0; i < 16; i++) m = fmaxf(m, red_s[i]);
    __syncthreads();

    float e = (tid < OO) ? expf(att_s[tid] - m) : 0.0f;
    float sv = e;
#pragma unroll
    for (int off = 16; off > 0; off >>= 1) sv += __shfl_xor_sync(0xffffffffu, sv, off);
    if ((tid & 31) == 0) red_s[tid >> 5] = sv;
    __syncthreads();
    float tot = 0.0f;
#pragma unroll
    for (int i = 0; i < 16; i++) tot += red_s[i];
    if (tid < OO) att_s[tid] = e / tot;
    __syncthreads();

    {
        const float* xtn = g_xt + (size_t)n * OO * CF;
        int q = tid >> 7, d = tid & 127;
        int o0 = q * 49;
        float a[8];
#pragma unroll
        for (int k = 0; k < 8; k++) a[k] = 0.0f;
#pragma unroll
        for (int i = 0; i < 48; i += 8) {
#pragma unroll
            for (int k = 0; k < 8; k++)
                a[k] = fmaf(att_s[o0 + i + k], xtn[(size_t)(o0 + i + k) * CF + d], a[k]);
        }
        a[0] = fmaf(att_s[o0 + 48], xtn[(size_t)(o0 + 48) * CF + d], a[0]);
        selp[q][d] = ((a[0] + a[1]) + (a[2] + a[3])) + ((a[4] + a[5]) + (a[6] + a[7]));
    }
    __syncthreads();
    if (tid < 128) {
        float s = (selp[0][tid] + selp[1][tid]) + (selp[2][tid] + selp[3][tid]);
        g_sel[n * CED + tid] = s;
        sel_s[tid] = s;
    } else if (tid == 128) {
        float a = 0.0f;
        for (int o = 0; o < OO; o++) a = fmaf(att_s[o], xcoord(o), a);
        g_sel[n * CED + 128] = a;
        sel_s[128] = a;
    } else if (tid == 129) {
        float a = 0.0f;
        for (int o = 0; o < OO; o++) a = fmaf(att_s[o], ycoord(o), a);
        g_sel[n * CED + 129] = a;
        sel_s[129] = a;
    }
    __syncthreads();

    {
        int p = tid >> 8, ch = tid & 255;
        int d0 = p * 65, d1 = d0 + 65;
        float s = 0.0f;
#pragma unroll 4
        for (int d = d0; d < d1; d++)
            s = fmaf(sel_s[d], gt_w0[(QD + d) * 256 + ch], s);
        pgp[p][ch] = s;
    }
    __syncthreads();
    if (tid < 256)
        g_pern_gt[n * 256 + tid] += pgp[0][tid] + pgp[1][tid];
}

// ---------------- f_phi head ----------------
__global__ void __launch_bounds__(256) k_fphi(const float* __restrict__ fp_w0,
                                              const float* __restrict__ fp_b0,
                                              const float* __restrict__ fp_w1,
                                              const float* __restrict__ fp_b1,
                                              float* __restrict__ out) {
    int n = blockIdx.x;
    int tid = threadIdx.x;
    __shared__ float f_s[FP];

    const float* rel = g_rel + n * GT;
    float s = fp_b0[tid];
#pragma unroll 4
    for (int h = 0; h < GT; h++)
        s = fmaf(rel[h], fp_w0[h * FP + tid], s);
    f_s[tid] = fmaxf(s, 0.0f);
    __syncthreads();

    if (tid < ASZ) {
        float s2 = fp_b1[tid];
#pragma unroll 4
        for (int h = 0; h < FP; h++)
            s2 = fmaf(f_s[h], fp_w1[h * ASZ + tid], s2);
        out[n * ASZ + tid] = s2;
    }
}

// ---------------- launch ----------------
extern "C" void kernel_launch(void* const* d_in, const int* in_sizes, int n_in,
                              void* d_out, int out_size) {
    const float* image  = (const float*)d_in[0];
    const float* code   = (const float*)d_in[1];
    const float* conv_w = (const float*)d_in[2];
    const float* conv_b = (const float*)d_in[3];
    const float* hp_w0  = (const float*)d_in[4];
    const float* hp_b0  = (const float*)d_in[5];
    const float* hp_w1  = (const float*)d_in[6];
    const float* hp_b1  = (const float*)d_in[7];
    const float* gt_w0  = (const float*)d_in[8];
    const float* gt_b0  = (const float*)d_in[9];
    const float* gt_w1  = (const float*)d_in[10];
    const float* gt_b1  = (const float*)d_in[11];
    const float* fp_w0  = (const float*)d_in[12];
    const float* fp_b0  = (const float*)d_in[13];
    const float* fp_w1  = (const float*)d_in[14];
    const float* fp_b1  = (const float*)d_in[15];
    float* out = (float*)d_out;

    cudaFuncSetAttribute(k_conv_mma, cudaFuncAttributeMaxDynamicSharedMemorySize, CONV_SMEM);
    cudaFuncSetAttribute(k_hpsi_mma, cudaFuncAttributeMaxDynamicSharedMemorySize, 115712);
    cudaFuncSetAttribute(k_gt_mma,   cudaFuncAttributeMaxDynamicSharedMemorySize, 214016);

    k_prep_all<<<PREP_BLOCKS, 256>>>(image, conv_w, code, hp_w0, hp_b0, gt_w0, gt_b0, gt_w1);
    k_conv_mma<<<NCTA, 512, CONV_SMEM>>>(conv_b);
    k_hpsi_mma<<<NT96, 512, 115712>>>(hp_w1, hp_b1);
    k_softsel<<<NB, 512>>>(gt_w0);
    k_gt_mma<<<NT96, 512, 214016>>>(gt_b1);
    k_fphi<<<NB, 256>>>(fp_w0, fp_b0, fp_w1, fp_b1, out);
}